// round 10
// baseline (speedup 1.0000x reference)
#include <cuda_runtime.h>
#include <cuda_bf16.h>
#include <cuda_fp16.h>
#include <math.h>
#include <stdint.h>

// ---------------------------------------------------------------------------
// Sea_Attention fused, round 10: fp16 HMMA, warp tile 64x64 (CTA 128x256),
// gate-first ordering with fp16 gate tensor.
//   prep -> reduce -> gemm0 -> attn -> gemm2 -> mm<1> -> dw -> mm<4>(gate)
//   -> mm<3>(proj * gate -> out)
// ---------------------------------------------------------------------------

#define BB 16

// ---------------- device scratch ----------------
__device__ float g_Wqkv[768*256];
__device__ float g_Wxx[2][512*512];
__device__ __half g_Wvg1_h[768*256];
__device__ __half g_Wfin_h[256*768];
__device__ float g_wdw[256*9];
__device__ float g_pos[4][128*64];
__device__ float g_xm[2][256*1024];
__device__ float g_q[2][128*1024];
__device__ float g_k[2][128*1024];
__device__ float g_vax[2][512*1024];
__device__ float g_ax[2][512*1024];
__device__ float g_xx[2][BB*512*64];
__device__ float g_g1[(size_t)BB*256*4096];   // gate intermediate 1 (pre-dw)
// fp16 activation tensors
__device__ __half g_xh[(size_t)BB*256*4096];
__device__ __half g_pb[(size_t)BB*512*4096];
__device__ __half g_g2b[(size_t)BB*256*4096];
__device__ __half g_gate[(size_t)BB*256*4096];

struct P32 { const float* p[32]; };

__device__ __forceinline__ float hsig(float x) {
    return fminf(fmaxf(x + 3.0f, 0.0f), 6.0f) * (1.0f / 6.0f);
}

__device__ __forceinline__ uint32_t smem_u32(const void* p) {
    uint32_t a;
    asm("{ .reg .u64 t; cvta.to.shared.u64 t, %1; cvt.u32.u64 %0, t; }" : "=r"(a) : "l"(p));
    return a;
}

__device__ __forceinline__ void mma16816(float (&d)[4], const uint32_t (&a)[4],
                                         uint32_t b0, uint32_t b1) {
    asm volatile(
        "mma.sync.aligned.m16n8k16.row.col.f32.f16.f16.f32 "
        "{%0,%1,%2,%3}, {%4,%5,%6,%7}, {%8,%9}, {%0,%1,%2,%3};"
        : "+f"(d[0]), "+f"(d[1]), "+f"(d[2]), "+f"(d[3])
        : "r"(a[0]), "r"(a[1]), "r"(a[2]), "r"(a[3]), "r"(b0), "r"(b1));
}

#define LDSM4(r, a) asm volatile( \
    "ldmatrix.sync.aligned.m8n8.x4.shared.b16 {%0,%1,%2,%3}, [%4];" \
    : "=r"((r)[0]),"=r"((r)[1]),"=r"((r)[2]),"=r"((r)[3]) : "r"(a))
#define LDSM4T(r, a) asm volatile( \
    "ldmatrix.sync.aligned.m8n8.x4.trans.shared.b16 {%0,%1,%2,%3}, [%4];" \
    : "=r"((r)[0]),"=r"((r)[1]),"=r"((r)[2]),"=r"((r)[3]) : "r"(a))
#define CP16(d, s) asm volatile( \
    "cp.async.cg.shared.global [%0], [%1], 16;" :: "r"(d), "l"(s))
#define CP_COMMIT() asm volatile("cp.async.commit_group;")
#define CP_WAIT(n)  asm volatile("cp.async.wait_group %0;" :: "n"(n))

__device__ __forceinline__ uint32_t hpack(float a, float b) {
    __half2 t = __floats2half2_rn(a, b);
    return *reinterpret_cast<uint32_t*>(&t);
}

// ---------------- prep ----------------
__global__ void prep_kernel(P32 ps) {
    int i = blockIdx.x * 256 + threadIdx.x;
    if (i < 196608) {                       // Wqkv fp32
        int r = i >> 8, k = i & 255;
        float v;
        if (r < 128)      v = ps.p[2][r]     * ps.p[1][r*256+k];
        else if (r < 256) v = ps.p[5][r-128] * ps.p[4][(r-128)*256+k];
        else              v = ps.p[8][r-256] * ps.p[7][(r-256)*256+k];
        g_Wqkv[i] = v; return;
    }
    i -= 196608;
    if (i < 196608) {                       // Wvg1 fp16
        int r = i >> 8, k = i & 255;
        float v = (r < 512) ? ps.p[8][r] * ps.p[7][r*256+k]
                            : ps.p[24][r-512] * ps.p[23][(r-512)*256+k];
        g_Wvg1_h[i] = __float2half_rn(v);
        return;
    }
    i -= 196608;
    if (i < 262144) { int r = i >> 9; g_Wxx[0][i] = ps.p[15][r] * ps.p[14][i]; return; }
    i -= 262144;
    if (i < 262144) { int r = i >> 9; g_Wxx[1][i] = ps.p[18][r] * ps.p[17][i]; return; }
    i -= 262144;
    if (i < 196608) {                       // Wfin fp16
        int r = i / 768, c = i % 768;
        float v = (c < 512) ? ps.p[21][r] * ps.p[20][r*512+c]
                            : ps.p[30][r] * ps.p[29][r*256+(c-512)];
        g_Wfin_h[i] = __float2half_rn(v);
        return;
    }
    i -= 196608;
    if (i < 2304) { g_wdw[i] = ps.p[27][i/9] * ps.p[26][i]; return; }
    i -= 2304;
    if (i < 32768) {
        int t = i >> 13, rest = i & 8191;
        int c = rest >> 6, n = rest & 63;
        float coord = 0.25f * (float)n - 0.375f;
        coord = fminf(fmaxf(coord, 0.0f), 15.0f);
        int lo = (int)floorf(coord);
        int hi = min(lo + 1, 15);
        float tf = coord - (float)lo;
        const float* src = ps.p[10 + t];
        g_pos[t][c*64 + n] = src[c*16+lo] * (1.0f - tf) + src[c*16+hi] * tf;
    }
}

// ---------------- reduce + x fp16 ----------------
__global__ void reduce_kernel(const float* __restrict__ x) {
    int bc = blockIdx.x;
    int b = bc >> 8, c = bc & 255;
    __shared__ float sm[64 * 65];
    int t = threadIdx.x;
    const float* xp = x + (size_t)bc * 4096;
    for (int i = t; i < 4096; i += 256)
        sm[(i >> 6) * 65 + (i & 63)] = xp[i];
    __syncthreads();
    if (t < 64) {
        float s = 0.f;
        #pragma unroll
        for (int w = 0; w < 64; w++) s += sm[t*65 + w];
        g_xm[0][c*1024 + b*64 + t] = s * (1.0f/64.0f);
    } else if (t < 128) {
        int w = t - 64;
        float s = 0.f;
        #pragma unroll
        for (int h = 0; h < 64; h++) s += sm[h*65 + w];
        g_xm[1][c*1024 + b*64 + w] = s * (1.0f/64.0f);
    }
    for (int i = t; i < 4096; i += 256)
        g_xh[(size_t)bc * 4096 + i] = __float2half_rn(sm[(i >> 6) * 65 + (i & 63)]);
}

// ---------------- axial attention ----------------
__global__ void attn_kernel() {
    int bid = blockIdx.x;
    int br = bid >> 7, b = (bid >> 3) & 15, h = bid & 7;
    __shared__ float qs[16][64], ks[16][64], vs[64][64], ps[64][65];
    int t = threadIdx.x;
    #pragma unroll
    for (int kd = 0; kd < 16; kd++) {
        qs[kd][t] = g_q[br][(h*16+kd)*1024 + b*64 + t];
        ks[kd][t] = g_k[br][(h*16+kd)*1024 + b*64 + t];
    }
    for (int d = 0; d < 64; d++)
        vs[d][t] = g_vax[br][(h*64+d)*1024 + b*64 + t];
    __syncthreads();
    float qreg[16];
    #pragma unroll
    for (int kd = 0; kd < 16; kd++) qreg[kd] = qs[kd][t];
    float mx = -1e30f;
    for (int m = 0; m < 64; m++) {
        float s = 0.f;
        #pragma unroll
        for (int kd = 0; kd < 16; kd++) s = fmaf(qreg[kd], ks[kd][m], s);
        s *= 0.25f;
        ps[t][m] = s;
        mx = fmaxf(mx, s);
    }
    float sum = 0.f;
    for (int m = 0; m < 64; m++) {
        float e = __expf(ps[t][m] - mx);
        ps[t][m] = e;
        sum += e;
    }
    float inv = 1.0f / sum;
    for (int d = 0; d < 64; d++) {
        float o = 0.f;
        for (int m = 0; m < 64; m++) o = fmaf(ps[t][m], vs[d][m], o);
        g_ax[br][(h*64+d)*1024 + b*64 + t] = o * inv;
    }
}

// ---------------- depthwise -> g2 fp16 ----------------
__global__ void dw_kernel(const float* __restrict__ b_dw) {
    int bc = blockIdx.x;
    int c = bc & 255;
    __shared__ float sm[64][65];
    const float* gp = &g_g1[(size_t)bc * 4096];
    int t = threadIdx.x;
    for (int i = t; i < 4096; i += 256) sm[i >> 6][i & 63] = gp[i];
    __syncthreads();
    float w9[9];
    #pragma unroll
    for (int j = 0; j < 9; j++) w9[j] = g_wdw[c*9 + j];
    float bias = b_dw[c];
    for (int i = t; i < 4096; i += 256) {
        int h = i >> 6, w = i & 63;
        float s = 0.f;
        #pragma unroll
        for (int di = 0; di < 3; di++) {
            int hh = h + di - 1;
            if ((unsigned)hh >= 64u) continue;
            #pragma unroll
            for (int dj = 0; dj < 3; dj++) {
                int ww = w + dj - 1;
                if ((unsigned)ww >= 64u) continue;
                s = fmaf(sm[hh][ww], w9[di*3 + dj], s);
            }
        }
        g_g2b[(size_t)bc * 4096 + i] = __float2half_rn(fmaxf(s + bias, 0.0f));
    }
}

// ---------------- small SIMT GEMM (modes 0 & 2) ----------------
#define BM 128
#define BN 64
#define BK 16

__device__ __forceinline__ void rank1(float (&A)[8][4], float4 a0, float4 a1, float4 b) {
    float ar[8] = {a0.x, a0.y, a0.z, a0.w, a1.x, a1.y, a1.z, a1.w};
    #pragma unroll
    for (int r = 0; r < 8; r++) {
        A[r][0] = fmaf(ar[r], b.x, A[r][0]);
        A[r][1] = fmaf(ar[r], b.y, A[r][1]);
        A[r][2] = fmaf(ar[r], b.z, A[r][2]);
        A[r][3] = fmaf(ar[r], b.w, A[r][3]);
    }
}

template <int MODE>
__global__ void __launch_bounds__(256, 2) gemm_k(
        const float* __restrict__ b0, const float* __restrict__ b1,
        const float* __restrict__ b2) {
    constexpr int K = (MODE == 0) ? 256 : 512;
    __shared__ float As[BK][BM + 4];
    __shared__ float Bs[BK][BN + 4];
    const int tid = threadIdx.x;
    const int bx = blockIdx.x, by = blockIdx.y, bz = blockIdx.z;
    const int ty8 = (tid >> 4) << 3;
    const int tx4 = (tid & 15) << 2;
    const int m0 = by * BM;
    const int pt = bx * BN;
    const float* Wm = (MODE == 0) ? g_Wqkv : g_Wxx[bz];
    const int wml = tid >> 1;
    const int wkg = (tid & 1) * 8;
    const int xkk = tid >> 4;
    const int xpl = (tid & 15) << 2;

    float acc[8][4];
    #pragma unroll
    for (int r = 0; r < 8; r++)
        #pragma unroll
        for (int j = 0; j < 4; j++) acc[r][j] = 0.f;

    for (int kt = 0; kt < K; kt += BK) {
        const float* wp = &Wm[(m0 + wml) * K + kt + wkg];
        float4 w0 = *(const float4*)wp;
        float4 w1 = *(const float4*)(wp + 4);
        int k = kt + xkk;
        float4 xv;
        if (MODE == 0) {
            xv = *(const float4*)&g_xm[bz][k*1024 + pt + xpl];
        } else {
            float4 t4 = *(const float4*)&g_ax[bz][k*1024 + pt + xpl];
            xv.x = fmaxf(t4.x, 0.f); xv.y = fmaxf(t4.y, 0.f);
            xv.z = fmaxf(t4.z, 0.f); xv.w = fmaxf(t4.w, 0.f);
        }
        __syncthreads();
        As[wkg+0][wml] = w0.x; As[wkg+1][wml] = w0.y;
        As[wkg+2][wml] = w0.z; As[wkg+3][wml] = w0.w;
        As[wkg+4][wml] = w1.x; As[wkg+5][wml] = w1.y;
        As[wkg+6][wml] = w1.z; As[wkg+7][wml] = w1.w;
        *(float4*)&Bs[xkk][xpl] = xv;
        __syncthreads();
        #pragma unroll
        for (int u = 0; u < BK; u++) {
            float4 a0 = *(const float4*)&As[u][ty8];
            float4 a1 = *(const float4*)&As[u][ty8 + 4];
            float4 bv = *(const float4*)&Bs[u][tx4];
            rank1(acc, a0, a1, bv);
        }
    }

    #pragma unroll
    for (int r = 0; r < 8; r++) {
        int m = m0 + ty8 + r;
        if (MODE == 0) {
            float4 o;
            if (m < 128) {
                float4 pv = *(const float4*)&g_pos[bz ? 2 : 0][m*64 + tx4];
                float bb = b0[m];
                o.x = acc[r][0] + bb + pv.x; o.y = acc[r][1] + bb + pv.y;
                o.z = acc[r][2] + bb + pv.z; o.w = acc[r][3] + bb + pv.w;
                *(float4*)&g_q[bz][m*1024 + pt + tx4] = o;
            } else if (m < 256) {
                int mm = m - 128;
                float4 pv = *(const float4*)&g_pos[bz ? 3 : 1][mm*64 + tx4];
                float bb = b1[mm];
                o.x = acc[r][0] + bb + pv.x; o.y = acc[r][1] + bb + pv.y;
                o.z = acc[r][2] + bb + pv.z; o.w = acc[r][3] + bb + pv.w;
                *(float4*)&g_k[bz][mm*1024 + pt + tx4] = o;
            } else {
                int mm = m - 256;
                float bb = b2[mm];
                o.x = acc[r][0] + bb; o.y = acc[r][1] + bb;
                o.z = acc[r][2] + bb; o.w = acc[r][3] + bb;
                *(float4*)&g_vax[bz][mm*1024 + pt + tx4] = o;
            }
        } else {
            float bb = (bz ? b2 : b1)[m];
            float4 o;
            o.x = acc[r][0] + bb; o.y = acc[r][1] + bb;
            o.z = acc[r][2] + bb; o.w = acc[r][3] + bb;
            int bidx = pt >> 6;
            *(float4*)&g_xx[bz][(bidx*512 + m)*64 + tx4] = o;
        }
    }
}

// ---------------- HMMA GEMM (modes 1, 3, 4) ----------------
// CTA 256 thr, tile 128(ch) x 256(px); 8 warps, warp grid 2(m) x 4(n),
// warp tile 64x64. fp16 x fp16, fp32 acc.
// Stage layout: A 0 (128 x 72 halves, 144B stride, 18432B)
//             | B 18432 (64 x 264 halves, 528B stride, 33792B)
// Stage stride 52224 B; 2 stages.
// MODE 1: W=Wvg1 (K=256), B=xh  -> p fp16 (relu(v+xx)) / g1 fp32 (+bias)
// MODE 3: W=Wfin[:,0:512],  B=pb  -> out = (proj + b) * gate
// MODE 4: W=Wfin[:,512:768], B=g2 -> gate = hsig(pw + b) fp16
#define MM_SMEM (2 * 52224)

template <int MODE>
__global__ void __launch_bounds__(256) mm_gemm(
        const float* __restrict__ bias0,
        const float* __restrict__ bias1,
        float* __restrict__ outp) {
    extern __shared__ char smem[];
    constexpr int K       = (MODE == 3) ? 512 : 256;
    constexpr int NC      = K / 64;
    constexpr int KSTRIDE = (MODE == 1) ? 256 : 768;
    constexpr int KOFF    = (MODE == 4) ? 512 : 0;
    constexpr int CH      = (MODE == 3) ? 512 : 256;
    const int tid = threadIdx.x, lane = tid & 31, wid = tid >> 5;
    const int wm = wid & 1, wn = wid >> 1;
    const int m0 = blockIdx.x * 128;
    const int pt = blockIdx.y;            // 256 px tiles: 16 per batch
    const int b_ = pt >> 4;
    const int hw0 = (pt & 15) << 8;

    const uint32_t sb = smem_u32(smem);
    const __half* Wh = (MODE == 1) ? g_Wvg1_h : g_Wfin_h;
    const __half* Bg = (MODE == 1) ? g_xh : (MODE == 3) ? g_pb : g_g2b;

    float acc[4][8][4];
    #pragma unroll
    for (int mf = 0; mf < 4; mf++)
        #pragma unroll
        for (int nf = 0; nf < 8; nf++)
            #pragma unroll
            for (int j = 0; j < 4; j++) acc[mf][nf][j] = 0.f;

    auto FILL = [&](int c) {
        const uint32_t st = sb + (uint32_t)(c & 1) * 52224u;
        const int kc = c * 64;
        #pragma unroll
        for (int i = 0; i < 4; i++) {          // A: 128 x 64 fp16
            int idx = tid + i * 256;
            int m = idx >> 3, k8 = (idx & 7) << 3;
            size_t g = (size_t)(m0 + m) * KSTRIDE + KOFF + kc + k8;
            CP16(st + (uint32_t)(m * 144 + k8 * 2), Wh + g);
        }
        #pragma unroll
        for (int i = 0; i < 8; i++) {          // B: 64 k x 256 px fp16
            int idx = tid + i * 256;
            int k = idx >> 5, px8 = (idx & 31) << 3;
            size_t g = (((size_t)(b_ * CH + kc + k)) << 12) + hw0 + px8;
            CP16(st + 18432u + (uint32_t)(k * 528 + px8 * 2), Bg + g);
        }
    };

    FILL(0); CP_COMMIT();
    for (int c = 0; c < NC; c++) {
        if (c + 1 < NC) { FILL(c + 1); CP_COMMIT(); CP_WAIT(1); }
        else            { CP_WAIT(0); }
        __syncthreads();
        const uint32_t st = sb + (uint32_t)(c & 1) * 52224u;
        #pragma unroll
        for (int kk = 0; kk < 64; kk += 16) {
            uint32_t ah[4][4];
            #pragma unroll
            for (int mf = 0; mf < 4; mf++) {
                uint32_t aoff = st + (uint32_t)(((wm * 64 + mf * 16 + (lane & 15)) * 72
                                  + kk + ((lane >> 4) << 3)) * 2);
                LDSM4(ah[mf], aoff);
            }
            #pragma unroll
            for (int ng = 0; ng < 4; ng++) {
                uint32_t bh[4];
                uint32_t boff = st + 18432u + (uint32_t)(
                    ((kk + (lane & 7) + (((lane >> 3) & 1) << 3)) * 264
                     + wn * 64 + ng * 16 + ((lane >> 4) << 3)) * 2);
                LDSM4T(bh, boff);
                #pragma unroll
                for (int mf = 0; mf < 4; mf++) {
                    mma16816(acc[mf][2*ng],   ah[mf], bh[0], bh[1]);
                    mma16816(acc[mf][2*ng+1], ah[mf], bh[2], bh[3]);
                }
            }
        }
        __syncthreads();
    }

    // ---- epilogue ----
    #pragma unroll
    for (int mf = 0; mf < 4; mf++) {
        int r0 = m0 + wm * 64 + mf * 16 + (lane >> 2);
        #pragma unroll
        for (int nf = 0; nf < 8; nf++) {
            int pxg = hw0 + wn * 64 + nf * 8 + ((lane & 3) << 1);
            #pragma unroll
            for (int half = 0; half < 2; half++) {
                int m = r0 + half * 8;
                float v0 = acc[mf][nf][half * 2 + 0];
                float v1 = acc[mf][nf][half * 2 + 1];
                if (MODE == 1) {
                    if (m < 512) {
                        float bb = bias0[m];
                        int hh = pxg >> 6, ww = pxg & 63;
                        float xr = g_xx[0][(b_*512 + m)*64 + hh];
                        float2 xc = *(const float2*)&g_xx[1][(b_*512 + m)*64 + ww];
                        float p0 = fmaxf(v0 + bb + xr + xc.x, 0.f);
                        float p1 = fmaxf(v1 + bb + xr + xc.y, 0.f);
                        size_t o = (((size_t)(b_*512 + m)) << 12) + pxg;
                        *(uint32_t*)&g_pb[o] = hpack(p0, p1);
                    } else {
                        float bb = bias1[m - 512];
                        float2 o2 = {v0 + bb, v1 + bb};
                        *(float2*)&g_g1[(((size_t)((b_ << 8) + m - 512)) << 12) + pxg] = o2;
                    }
                } else if (MODE == 4) {
                    float bb = bias0[m];
                    size_t o = (((size_t)((b_ << 8) + m)) << 12) + pxg;
                    *(uint32_t*)&g_gate[o] = hpack(hsig(v0 + bb), hsig(v1 + bb));
                } else {
                    float bb = bias0[m];
                    size_t o = (((size_t)((b_ << 8) + m)) << 12) + pxg;
                    uint32_t gv = *(const uint32_t*)&g_gate[o];
                    __half2 gh = *reinterpret_cast<__half2*>(&gv);
                    float2 g2 = __half22float2(gh);
                    float2 o2 = {(v0 + bb) * g2.x, (v1 + bb) * g2.y};
                    *(float2*)&outp[o] = o2;
                }
            }
        }
    }
}

// ---------------------------------------------------------------------------
extern "C" void kernel_launch(void* const* d_in, const int* in_sizes, int n_in,
                              void* d_out, int out_size) {
    (void)in_sizes; (void)n_in; (void)out_size;
    P32 ps;
    for (int i = 0; i < 32; i++) ps.p[i] = (const float*)d_in[i];
    const float* x      = ps.p[0];
    const float* bq     = ps.p[3];
    const float* bk     = ps.p[6];
    const float* bv     = ps.p[9];
    const float* b_row  = ps.p[16];
    const float* b_col  = ps.p[19];
    const float* b_proj = ps.p[22];
    const float* b_sc   = ps.p[25];
    const float* b_dw   = ps.p[28];
    const float* b_pw   = ps.p[31];
    float* out = (float*)d_out;

    cudaFuncSetAttribute(mm_gemm<1>, cudaFuncAttributeMaxDynamicSharedMemorySize, MM_SMEM);
    cudaFuncSetAttribute(mm_gemm<3>, cudaFuncAttributeMaxDynamicSharedMemorySize, MM_SMEM);
    cudaFuncSetAttribute(mm_gemm<4>, cudaFuncAttributeMaxDynamicSharedMemorySize, MM_SMEM);

    prep_kernel<<<4489, 256>>>(ps);
    reduce_kernel<<<4096, 256>>>(x);
    gemm_k<0><<<dim3(16, 6, 2), 256>>>(bq, bk, bv);
    attn_kernel<<<256, 64>>>();
    gemm_k<2><<<dim3(16, 4, 2), 256>>>(nullptr, b_row, b_col);
    mm_gemm<1><<<dim3(6, 256), 256, MM_SMEM>>>(bv, b_sc, nullptr);
    dw_kernel<<<4096, 256>>>(b_dw);
    mm_gemm<4><<<dim3(2, 256), 256, MM_SMEM>>>(b_pw, nullptr, nullptr);
    mm_gemm<3><<<dim3(2, 256), 256, MM_SMEM>>>(b_proj, nullptr, out);
}

// round 12
// speedup vs baseline: 1.2478x; 1.2478x over previous
#include <cuda_runtime.h>
#include <cuda_bf16.h>
#include <cuda_fp16.h>
#include <math.h>
#include <stdint.h>

// ---------------------------------------------------------------------------
// Sea_Attention fused, round 11: round-9 mm_gemm tile (warp 32x64, CTA
// 128x128, 2 CTA/SM) + gate-first fp16 ordering from round 10.
//   prep -> reduce -> gemm0 -> attn -> gemm2 -> mm<1> -> dw -> mm<4>(gate)
//   -> mm<3>(proj * gate -> out)
// ---------------------------------------------------------------------------

#define BB 16

// ---------------- device scratch ----------------
__device__ float g_Wqkv[768*256];
__device__ float g_Wxx[2][512*512];
__device__ __half g_Wvg1_h[768*256];
__device__ __half g_Wfin_h[256*768];
__device__ float g_wdw[256*9];
__device__ float g_pos[4][128*64];
__device__ float g_xm[2][256*1024];
__device__ float g_q[2][128*1024];
__device__ float g_k[2][128*1024];
__device__ float g_vax[2][512*1024];
__device__ float g_ax[2][512*1024];
__device__ float g_xx[2][BB*512*64];
__device__ float g_g1[(size_t)BB*256*4096];   // gate intermediate 1 (pre-dw)
// fp16 activation tensors
__device__ __half g_xh[(size_t)BB*256*4096];
__device__ __half g_pb[(size_t)BB*512*4096];
__device__ __half g_g2b[(size_t)BB*256*4096];
__device__ __half g_gate[(size_t)BB*256*4096];

struct P32 { const float* p[32]; };

__device__ __forceinline__ float hsig(float x) {
    return fminf(fmaxf(x + 3.0f, 0.0f), 6.0f) * (1.0f / 6.0f);
}

__device__ __forceinline__ uint32_t smem_u32(const void* p) {
    uint32_t a;
    asm("{ .reg .u64 t; cvta.to.shared.u64 t, %1; cvt.u32.u64 %0, t; }" : "=r"(a) : "l"(p));
    return a;
}

__device__ __forceinline__ void mma16816(float (&d)[4], const uint32_t (&a)[4],
                                         uint32_t b0, uint32_t b1) {
    asm volatile(
        "mma.sync.aligned.m16n8k16.row.col.f32.f16.f16.f32 "
        "{%0,%1,%2,%3}, {%4,%5,%6,%7}, {%8,%9}, {%0,%1,%2,%3};"
        : "+f"(d[0]), "+f"(d[1]), "+f"(d[2]), "+f"(d[3])
        : "r"(a[0]), "r"(a[1]), "r"(a[2]), "r"(a[3]), "r"(b0), "r"(b1));
}

#define LDSM4(r, a) asm volatile( \
    "ldmatrix.sync.aligned.m8n8.x4.shared.b16 {%0,%1,%2,%3}, [%4];" \
    : "=r"((r)[0]),"=r"((r)[1]),"=r"((r)[2]),"=r"((r)[3]) : "r"(a))
#define LDSM4T(r, a) asm volatile( \
    "ldmatrix.sync.aligned.m8n8.x4.trans.shared.b16 {%0,%1,%2,%3}, [%4];" \
    : "=r"((r)[0]),"=r"((r)[1]),"=r"((r)[2]),"=r"((r)[3]) : "r"(a))
#define CP16(d, s) asm volatile( \
    "cp.async.cg.shared.global [%0], [%1], 16;" :: "r"(d), "l"(s))
#define CP_COMMIT() asm volatile("cp.async.commit_group;")
#define CP_WAIT(n)  asm volatile("cp.async.wait_group %0;" :: "n"(n))

__device__ __forceinline__ uint32_t hpack(float a, float b) {
    __half2 t = __floats2half2_rn(a, b);
    return *reinterpret_cast<uint32_t*>(&t);
}

// ---------------- prep ----------------
__global__ void prep_kernel(P32 ps) {
    int i = blockIdx.x * 256 + threadIdx.x;
    if (i < 196608) {                       // Wqkv fp32
        int r = i >> 8, k = i & 255;
        float v;
        if (r < 128)      v = ps.p[2][r]     * ps.p[1][r*256+k];
        else if (r < 256) v = ps.p[5][r-128] * ps.p[4][(r-128)*256+k];
        else              v = ps.p[8][r-256] * ps.p[7][(r-256)*256+k];
        g_Wqkv[i] = v; return;
    }
    i -= 196608;
    if (i < 196608) {                       // Wvg1 fp16
        int r = i >> 8, k = i & 255;
        float v = (r < 512) ? ps.p[8][r] * ps.p[7][r*256+k]
                            : ps.p[24][r-512] * ps.p[23][(r-512)*256+k];
        g_Wvg1_h[i] = __float2half_rn(v);
        return;
    }
    i -= 196608;
    if (i < 262144) { int r = i >> 9; g_Wxx[0][i] = ps.p[15][r] * ps.p[14][i]; return; }
    i -= 262144;
    if (i < 262144) { int r = i >> 9; g_Wxx[1][i] = ps.p[18][r] * ps.p[17][i]; return; }
    i -= 262144;
    if (i < 196608) {                       // Wfin fp16
        int r = i / 768, c = i % 768;
        float v = (c < 512) ? ps.p[21][r] * ps.p[20][r*512+c]
                            : ps.p[30][r] * ps.p[29][r*256+(c-512)];
        g_Wfin_h[i] = __float2half_rn(v);
        return;
    }
    i -= 196608;
    if (i < 2304) { g_wdw[i] = ps.p[27][i/9] * ps.p[26][i]; return; }
    i -= 2304;
    if (i < 32768) {
        int t = i >> 13, rest = i & 8191;
        int c = rest >> 6, n = rest & 63;
        float coord = 0.25f * (float)n - 0.375f;
        coord = fminf(fmaxf(coord, 0.0f), 15.0f);
        int lo = (int)floorf(coord);
        int hi = min(lo + 1, 15);
        float tf = coord - (float)lo;
        const float* src = ps.p[10 + t];
        g_pos[t][c*64 + n] = src[c*16+lo] * (1.0f - tf) + src[c*16+hi] * tf;
    }
}

// ---------------- reduce + x fp16 ----------------
__global__ void reduce_kernel(const float* __restrict__ x) {
    int bc = blockIdx.x;
    int b = bc >> 8, c = bc & 255;
    __shared__ float sm[64 * 65];
    int t = threadIdx.x;
    const float* xp = x + (size_t)bc * 4096;
    for (int i = t; i < 4096; i += 256)
        sm[(i >> 6) * 65 + (i & 63)] = xp[i];
    __syncthreads();
    if (t < 64) {
        float s = 0.f;
        #pragma unroll
        for (int w = 0; w < 64; w++) s += sm[t*65 + w];
        g_xm[0][c*1024 + b*64 + t] = s * (1.0f/64.0f);
    } else if (t < 128) {
        int w = t - 64;
        float s = 0.f;
        #pragma unroll
        for (int h = 0; h < 64; h++) s += sm[h*65 + w];
        g_xm[1][c*1024 + b*64 + w] = s * (1.0f/64.0f);
    }
    for (int i = t; i < 4096; i += 256)
        g_xh[(size_t)bc * 4096 + i] = __float2half_rn(sm[(i >> 6) * 65 + (i & 63)]);
}

// ---------------- axial attention ----------------
__global__ void attn_kernel() {
    int bid = blockIdx.x;
    int br = bid >> 7, b = (bid >> 3) & 15, h = bid & 7;
    __shared__ float qs[16][64], ks[16][64], vs[64][64], ps[64][65];
    int t = threadIdx.x;
    #pragma unroll
    for (int kd = 0; kd < 16; kd++) {
        qs[kd][t] = g_q[br][(h*16+kd)*1024 + b*64 + t];
        ks[kd][t] = g_k[br][(h*16+kd)*1024 + b*64 + t];
    }
    for (int d = 0; d < 64; d++)
        vs[d][t] = g_vax[br][(h*64+d)*1024 + b*64 + t];
    __syncthreads();
    float qreg[16];
    #pragma unroll
    for (int kd = 0; kd < 16; kd++) qreg[kd] = qs[kd][t];
    float mx = -1e30f;
    for (int m = 0; m < 64; m++) {
        float s = 0.f;
        #pragma unroll
        for (int kd = 0; kd < 16; kd++) s = fmaf(qreg[kd], ks[kd][m], s);
        s *= 0.25f;
        ps[t][m] = s;
        mx = fmaxf(mx, s);
    }
    float sum = 0.f;
    for (int m = 0; m < 64; m++) {
        float e = __expf(ps[t][m] - mx);
        ps[t][m] = e;
        sum += e;
    }
    float inv = 1.0f / sum;
    for (int d = 0; d < 64; d++) {
        float o = 0.f;
        for (int m = 0; m < 64; m++) o = fmaf(ps[t][m], vs[d][m], o);
        g_ax[br][(h*64+d)*1024 + b*64 + t] = o * inv;
    }
}

// ---------------- depthwise -> g2 fp16 ----------------
__global__ void dw_kernel(const float* __restrict__ b_dw) {
    int bc = blockIdx.x;
    int c = bc & 255;
    __shared__ float sm[64][65];
    const float* gp = &g_g1[(size_t)bc * 4096];
    int t = threadIdx.x;
    for (int i = t; i < 4096; i += 256) sm[i >> 6][i & 63] = gp[i];
    __syncthreads();
    float w9[9];
    #pragma unroll
    for (int j = 0; j < 9; j++) w9[j] = g_wdw[c*9 + j];
    float bias = b_dw[c];
    for (int i = t; i < 4096; i += 256) {
        int h = i >> 6, w = i & 63;
        float s = 0.f;
        #pragma unroll
        for (int di = 0; di < 3; di++) {
            int hh = h + di - 1;
            if ((unsigned)hh >= 64u) continue;
            #pragma unroll
            for (int dj = 0; dj < 3; dj++) {
                int ww = w + dj - 1;
                if ((unsigned)ww >= 64u) continue;
                s = fmaf(sm[hh][ww], w9[di*3 + dj], s);
            }
        }
        g_g2b[(size_t)bc * 4096 + i] = __float2half_rn(fmaxf(s + bias, 0.0f));
    }
}

// ---------------- small SIMT GEMM (modes 0 & 2) ----------------
#define BM 128
#define BN 64
#define BK 16

__device__ __forceinline__ void rank1(float (&A)[8][4], float4 a0, float4 a1, float4 b) {
    float ar[8] = {a0.x, a0.y, a0.z, a0.w, a1.x, a1.y, a1.z, a1.w};
    #pragma unroll
    for (int r = 0; r < 8; r++) {
        A[r][0] = fmaf(ar[r], b.x, A[r][0]);
        A[r][1] = fmaf(ar[r], b.y, A[r][1]);
        A[r][2] = fmaf(ar[r], b.z, A[r][2]);
        A[r][3] = fmaf(ar[r], b.w, A[r][3]);
    }
}

template <int MODE>
__global__ void __launch_bounds__(256, 2) gemm_k(
        const float* __restrict__ b0, const float* __restrict__ b1,
        const float* __restrict__ b2) {
    constexpr int K = (MODE == 0) ? 256 : 512;
    __shared__ float As[BK][BM + 4];
    __shared__ float Bs[BK][BN + 4];
    const int tid = threadIdx.x;
    const int bx = blockIdx.x, by = blockIdx.y, bz = blockIdx.z;
    const int ty8 = (tid >> 4) << 3;
    const int tx4 = (tid & 15) << 2;
    const int m0 = by * BM;
    const int pt = bx * BN;
    const float* Wm = (MODE == 0) ? g_Wqkv : g_Wxx[bz];
    const int wml = tid >> 1;
    const int wkg = (tid & 1) * 8;
    const int xkk = tid >> 4;
    const int xpl = (tid & 15) << 2;

    float acc[8][4];
    #pragma unroll
    for (int r = 0; r < 8; r++)
        #pragma unroll
        for (int j = 0; j < 4; j++) acc[r][j] = 0.f;

    for (int kt = 0; kt < K; kt += BK) {
        const float* wp = &Wm[(m0 + wml) * K + kt + wkg];
        float4 w0 = *(const float4*)wp;
        float4 w1 = *(const float4*)(wp + 4);
        int k = kt + xkk;
        float4 xv;
        if (MODE == 0) {
            xv = *(const float4*)&g_xm[bz][k*1024 + pt + xpl];
        } else {
            float4 t4 = *(const float4*)&g_ax[bz][k*1024 + pt + xpl];
            xv.x = fmaxf(t4.x, 0.f); xv.y = fmaxf(t4.y, 0.f);
            xv.z = fmaxf(t4.z, 0.f); xv.w = fmaxf(t4.w, 0.f);
        }
        __syncthreads();
        As[wkg+0][wml] = w0.x; As[wkg+1][wml] = w0.y;
        As[wkg+2][wml] = w0.z; As[wkg+3][wml] = w0.w;
        As[wkg+4][wml] = w1.x; As[wkg+5][wml] = w1.y;
        As[wkg+6][wml] = w1.z; As[wkg+7][wml] = w1.w;
        *(float4*)&Bs[xkk][xpl] = xv;
        __syncthreads();
        #pragma unroll
        for (int u = 0; u < BK; u++) {
            float4 a0 = *(const float4*)&As[u][ty8];
            float4 a1 = *(const float4*)&As[u][ty8 + 4];
            float4 bv = *(const float4*)&Bs[u][tx4];
            rank1(acc, a0, a1, bv);
        }
    }

    #pragma unroll
    for (int r = 0; r < 8; r++) {
        int m = m0 + ty8 + r;
        if (MODE == 0) {
            float4 o;
            if (m < 128) {
                float4 pv = *(const float4*)&g_pos[bz ? 2 : 0][m*64 + tx4];
                float bb = b0[m];
                o.x = acc[r][0] + bb + pv.x; o.y = acc[r][1] + bb + pv.y;
                o.z = acc[r][2] + bb + pv.z; o.w = acc[r][3] + bb + pv.w;
                *(float4*)&g_q[bz][m*1024 + pt + tx4] = o;
            } else if (m < 256) {
                int mm = m - 128;
                float4 pv = *(const float4*)&g_pos[bz ? 3 : 1][mm*64 + tx4];
                float bb = b1[mm];
                o.x = acc[r][0] + bb + pv.x; o.y = acc[r][1] + bb + pv.y;
                o.z = acc[r][2] + bb + pv.z; o.w = acc[r][3] + bb + pv.w;
                *(float4*)&g_k[bz][mm*1024 + pt + tx4] = o;
            } else {
                int mm = m - 256;
                float bb = b2[mm];
                o.x = acc[r][0] + bb; o.y = acc[r][1] + bb;
                o.z = acc[r][2] + bb; o.w = acc[r][3] + bb;
                *(float4*)&g_vax[bz][mm*1024 + pt + tx4] = o;
            }
        } else {
            float bb = (bz ? b2 : b1)[m];
            float4 o;
            o.x = acc[r][0] + bb; o.y = acc[r][1] + bb;
            o.z = acc[r][2] + bb; o.w = acc[r][3] + bb;
            int bidx = pt >> 6;
            *(float4*)&g_xx[bz][(bidx*512 + m)*64 + tx4] = o;
        }
    }
}

// ---------------- HMMA GEMM (modes 1, 3, 4) ----------------
// CTA 256 thr, tile 128(ch) x 128(px); warps 4x2, warp tile 32x64.
// Pure fp16 x fp16, fp32 acc.
// Stage layout: A 0 (128x72 halves, 144B stride) | B 18432 (64x136, 272B)
// Stage stride 35840 B; 2 stages.  (2 CTA/SM)
// MODE 1: W=Wvg1 (K=256), B=xh  -> p fp16 (relu(v+xx)) / g1 fp32 (+bias)
// MODE 4: W=Wfin[:,512:768], B=g2 -> gate = hsig(pw + b) fp16
// MODE 3: W=Wfin[:,0:512],  B=pb  -> out = (proj + b) * gate
#define MM_SMEM (2 * 35840)

template <int MODE>
__global__ void __launch_bounds__(256) mm_gemm(
        const float* __restrict__ bias0,
        const float* __restrict__ bias1,
        float* __restrict__ outp) {
    extern __shared__ char smem[];
    constexpr int K       = (MODE == 3) ? 512 : 256;
    constexpr int NC      = K / 64;
    constexpr int KSTRIDE = (MODE == 1) ? 256 : 768;
    constexpr int KOFF    = (MODE == 4) ? 512 : 0;
    constexpr int CH      = (MODE == 3) ? 512 : 256;
    const int tid = threadIdx.x, lane = tid & 31, wid = tid >> 5;
    const int wm = wid & 3, wn = wid >> 2;
    const int m0 = blockIdx.x * 128;
    const int pt = blockIdx.y;
    const int b_ = pt >> 5;
    const int hw0 = (pt & 31) << 7;

    const uint32_t sb = smem_u32(smem);
    const __half* Wh = (MODE == 1) ? g_Wvg1_h : g_Wfin_h;
    const __half* Bg = (MODE == 1) ? g_xh : (MODE == 3) ? g_pb : g_g2b;

    float acc[2][8][4];
    #pragma unroll
    for (int mf = 0; mf < 2; mf++)
        #pragma unroll
        for (int nf = 0; nf < 8; nf++)
            #pragma unroll
            for (int j = 0; j < 4; j++) acc[mf][nf][j] = 0.f;

    auto FILL = [&](int c) {
        const uint32_t st = sb + (uint32_t)(c & 1) * 35840u;
        const int kc = c * 64;
        #pragma unroll
        for (int i = 0; i < 4; i++) {          // A: 128x64 fp16
            int idx = tid + i * 256;
            int m = idx >> 3, k8 = (idx & 7) << 3;
            size_t g = (size_t)(m0 + m) * KSTRIDE + KOFF + kc + k8;
            CP16(st + (uint32_t)(m * 144 + k8 * 2), Wh + g);
        }
        #pragma unroll
        for (int i = 0; i < 4; i++) {          // B: 64k x 128px fp16
            int idx = tid + i * 256;
            int k = idx >> 4, px8 = (idx & 15) << 3;
            size_t g = (((size_t)(b_ * CH + kc + k)) << 12) + hw0 + px8;
            CP16(st + 18432u + (uint32_t)(k * 272 + px8 * 2), Bg + g);
        }
    };

    FILL(0); CP_COMMIT();
    for (int c = 0; c < NC; c++) {
        if (c + 1 < NC) { FILL(c + 1); CP_COMMIT(); CP_WAIT(1); }
        else            { CP_WAIT(0); }
        __syncthreads();
        const uint32_t st = sb + (uint32_t)(c & 1) * 35840u;
        #pragma unroll
        for (int kk = 0; kk < 64; kk += 16) {
            uint32_t ah[2][4];
            uint32_t aoff = st + (uint32_t)(((wm * 32 + (lane & 15)) * 72
                              + kk + ((lane >> 4) << 3)) * 2);
            LDSM4(ah[0], aoff);
            LDSM4(ah[1], aoff + 16u * 144u);
            #pragma unroll
            for (int np = 0; np < 4; np++) {
                uint32_t bh[4];
                uint32_t boff = st + 18432u + (uint32_t)(
                    ((kk + (lane & 7) + (((lane >> 3) & 1) << 3)) * 136
                     + wn * 64 + np * 16 + ((lane >> 4) << 3)) * 2);
                LDSM4T(bh, boff);
                #pragma unroll
                for (int mf = 0; mf < 2; mf++) {
                    mma16816(acc[mf][2*np],   ah[mf], bh[0], bh[1]);
                    mma16816(acc[mf][2*np+1], ah[mf], bh[2], bh[3]);
                }
            }
        }
        __syncthreads();
    }

    // ---- epilogue ----
    #pragma unroll
    for (int mf = 0; mf < 2; mf++) {
        int r0 = m0 + wm * 32 + mf * 16 + (lane >> 2);
        #pragma unroll
        for (int nf = 0; nf < 8; nf++) {
            int pxg = hw0 + wn * 64 + nf * 8 + ((lane & 3) << 1);
            #pragma unroll
            for (int half = 0; half < 2; half++) {
                int m = r0 + half * 8;
                float v0 = acc[mf][nf][half * 2 + 0];
                float v1 = acc[mf][nf][half * 2 + 1];
                if (MODE == 1) {
                    if (m < 512) {
                        float bb = bias0[m];
                        int hh = pxg >> 6, ww = pxg & 63;
                        float xr = g_xx[0][(b_*512 + m)*64 + hh];
                        float2 xc = *(const float2*)&g_xx[1][(b_*512 + m)*64 + ww];
                        float p0 = fmaxf(v0 + bb + xr + xc.x, 0.f);
                        float p1 = fmaxf(v1 + bb + xr + xc.y, 0.f);
                        size_t o = (((size_t)(b_*512 + m)) << 12) + pxg;
                        *(uint32_t*)&g_pb[o] = hpack(p0, p1);
                    } else {
                        float bb = bias1[m - 512];
                        float2 o2 = {v0 + bb, v1 + bb};
                        *(float2*)&g_g1[(((size_t)((b_ << 8) + m - 512)) << 12) + pxg] = o2;
                    }
                } else if (MODE == 4) {
                    float bb = bias0[m];
                    size_t o = (((size_t)((b_ << 8) + m)) << 12) + pxg;
                    *(uint32_t*)&g_gate[o] = hpack(hsig(v0 + bb), hsig(v1 + bb));
                } else {
                    float bb = bias0[m];
                    size_t o = (((size_t)((b_ << 8) + m)) << 12) + pxg;
                    uint32_t gv = *(const uint32_t*)&g_gate[o];
                    __half2 gh = *reinterpret_cast<__half2*>(&gv);
                    float2 g2 = __half22float2(gh);
                    float2 o2 = {(v0 + bb) * g2.x, (v1 + bb) * g2.y};
                    *(float2*)&outp[o] = o2;
                }
            }
        }
    }
}

// ---------------------------------------------------------------------------
extern "C" void kernel_launch(void* const* d_in, const int* in_sizes, int n_in,
                              void* d_out, int out_size) {
    (void)in_sizes; (void)n_in; (void)out_size;
    P32 ps;
    for (int i = 0; i < 32; i++) ps.p[i] = (const float*)d_in[i];
    const float* x      = ps.p[0];
    const float* bq     = ps.p[3];
    const float* bk     = ps.p[6];
    const float* bv     = ps.p[9];
    const float* b_row  = ps.p[16];
    const float* b_col  = ps.p[19];
    const float* b_proj = ps.p[22];
    const float* b_sc   = ps.p[25];
    const float* b_dw   = ps.p[28];
    const float* b_pw   = ps.p[31];
    float* out = (float*)d_out;

    cudaFuncSetAttribute(mm_gemm<1>, cudaFuncAttributeMaxDynamicSharedMemorySize, MM_SMEM);
    cudaFuncSetAttribute(mm_gemm<3>, cudaFuncAttributeMaxDynamicSharedMemorySize, MM_SMEM);
    cudaFuncSetAttribute(mm_gemm<4>, cudaFuncAttributeMaxDynamicSharedMemorySize, MM_SMEM);

    prep_kernel<<<4489, 256>>>(ps);
    reduce_kernel<<<4096, 256>>>(x);
    gemm_k<0><<<dim3(16, 6, 2), 256>>>(bq, bk, bv);
    attn_kernel<<<256, 64>>>();
    gemm_k<2><<<dim3(16, 4, 2), 256>>>(nullptr, b_row, b_col);
    mm_gemm<1><<<dim3(6, 512), 256, MM_SMEM>>>(bv, b_sc, nullptr);
    dw_kernel<<<4096, 256>>>(b_dw);
    mm_gemm<4><<<dim3(2, 512), 256, MM_SMEM>>>(b_pw, nullptr, nullptr);
    mm_gemm<3><<<dim3(2, 512), 256, MM_SMEM>>>(b_proj, nullptr, out);
}

// round 13
// speedup vs baseline: 1.2530x; 1.0041x over previous
#include <cuda_runtime.h>
#include <cuda_bf16.h>
#include <cuda_fp16.h>
#include <math.h>
#include <stdint.h>

// ---------------------------------------------------------------------------
// Sea_Attention fused, round 13: attack the non-MMA floor.
//  - g1 intermediate fp16
//  - attn kernel 256 threads (4x parallelism)
//  - mm_gemm 3-stage cp.async pipeline, one sync per chunk
//  - prep+reduce merged into one launch
// ---------------------------------------------------------------------------

#define BB 16

// ---------------- device scratch ----------------
__device__ float g_Wqkv[768*256];
__device__ float g_Wxx[2][512*512];
__device__ __half g_Wvg1_h[768*256];
__device__ __half g_Wfin_h[256*768];
__device__ float g_wdw[256*9];
__device__ float g_pos[4][128*64];
__device__ float g_xm[2][256*1024];
__device__ float g_q[2][128*1024];
__device__ float g_k[2][128*1024];
__device__ float g_vax[2][512*1024];
__device__ float g_ax[2][512*1024];
__device__ float g_xx[2][BB*512*64];
// fp16 activation tensors
__device__ __half g_g1h[(size_t)BB*256*4096];
__device__ __half g_xh[(size_t)BB*256*4096];
__device__ __half g_pb[(size_t)BB*512*4096];
__device__ __half g_g2b[(size_t)BB*256*4096];
__device__ __half g_gate[(size_t)BB*256*4096];

struct P32 { const float* p[32]; };

__device__ __forceinline__ float hsig(float x) {
    return fminf(fmaxf(x + 3.0f, 0.0f), 6.0f) * (1.0f / 6.0f);
}

__device__ __forceinline__ uint32_t smem_u32(const void* p) {
    uint32_t a;
    asm("{ .reg .u64 t; cvta.to.shared.u64 t, %1; cvt.u32.u64 %0, t; }" : "=r"(a) : "l"(p));
    return a;
}

__device__ __forceinline__ void mma16816(float (&d)[4], const uint32_t (&a)[4],
                                         uint32_t b0, uint32_t b1) {
    asm volatile(
        "mma.sync.aligned.m16n8k16.row.col.f32.f16.f16.f32 "
        "{%0,%1,%2,%3}, {%4,%5,%6,%7}, {%8,%9}, {%0,%1,%2,%3};"
        : "+f"(d[0]), "+f"(d[1]), "+f"(d[2]), "+f"(d[3])
        : "r"(a[0]), "r"(a[1]), "r"(a[2]), "r"(a[3]), "r"(b0), "r"(b1));
}

#define LDSM4(r, a) asm volatile( \
    "ldmatrix.sync.aligned.m8n8.x4.shared.b16 {%0,%1,%2,%3}, [%4];" \
    : "=r"((r)[0]),"=r"((r)[1]),"=r"((r)[2]),"=r"((r)[3]) : "r"(a))
#define LDSM4T(r, a) asm volatile( \
    "ldmatrix.sync.aligned.m8n8.x4.trans.shared.b16 {%0,%1,%2,%3}, [%4];" \
    : "=r"((r)[0]),"=r"((r)[1]),"=r"((r)[2]),"=r"((r)[3]) : "r"(a))
#define CP16(d, s) asm volatile( \
    "cp.async.cg.shared.global [%0], [%1], 16;" :: "r"(d), "l"(s))
#define CP_COMMIT() asm volatile("cp.async.commit_group;")
#define CP_WAIT(n)  asm volatile("cp.async.wait_group %0;" :: "n"(n))

__device__ __forceinline__ uint32_t hpack(float a, float b) {
    __half2 t = __floats2half2_rn(a, b);
    return *reinterpret_cast<uint32_t*>(&t);
}

// ---------------- merged prep + reduce ----------------
// blocks [0, 4096): reduce (row/col means of x + fp16 split)
// blocks [4096, 8585): prep (weight folding, pos tables)
__global__ void prep_reduce_kernel(P32 ps, const float* __restrict__ x) {
    __shared__ float sm[64 * 65];
    if (blockIdx.x < 4096) {
        int bc = blockIdx.x;
        int b = bc >> 8, c = bc & 255;
        int t = threadIdx.x;
        const float* xp = x + (size_t)bc * 4096;
        for (int i = t; i < 4096; i += 256)
            sm[(i >> 6) * 65 + (i & 63)] = xp[i];
        __syncthreads();
        if (t < 64) {
            float s = 0.f;
            #pragma unroll
            for (int w = 0; w < 64; w++) s += sm[t*65 + w];
            g_xm[0][c*1024 + b*64 + t] = s * (1.0f/64.0f);
        } else if (t < 128) {
            int w = t - 64;
            float s = 0.f;
            #pragma unroll
            for (int h = 0; h < 64; h++) s += sm[h*65 + w];
            g_xm[1][c*1024 + b*64 + w] = s * (1.0f/64.0f);
        }
        for (int i = t; i < 4096; i += 256)
            g_xh[(size_t)bc * 4096 + i] = __float2half_rn(sm[(i >> 6) * 65 + (i & 63)]);
        return;
    }
    int i = (blockIdx.x - 4096) * 256 + threadIdx.x;
    if (i < 196608) {                       // Wqkv fp32
        int r = i >> 8, k = i & 255;
        float v;
        if (r < 128)      v = ps.p[2][r]     * ps.p[1][r*256+k];
        else if (r < 256) v = ps.p[5][r-128] * ps.p[4][(r-128)*256+k];
        else              v = ps.p[8][r-256] * ps.p[7][(r-256)*256+k];
        g_Wqkv[i] = v; return;
    }
    i -= 196608;
    if (i < 196608) {                       // Wvg1 fp16
        int r = i >> 8, k = i & 255;
        float v = (r < 512) ? ps.p[8][r] * ps.p[7][r*256+k]
                            : ps.p[24][r-512] * ps.p[23][(r-512)*256+k];
        g_Wvg1_h[i] = __float2half_rn(v);
        return;
    }
    i -= 196608;
    if (i < 262144) { int r = i >> 9; g_Wxx[0][i] = ps.p[15][r] * ps.p[14][i]; return; }
    i -= 262144;
    if (i < 262144) { int r = i >> 9; g_Wxx[1][i] = ps.p[18][r] * ps.p[17][i]; return; }
    i -= 262144;
    if (i < 196608) {                       // Wfin fp16
        int r = i / 768, c = i % 768;
        float v = (c < 512) ? ps.p[21][r] * ps.p[20][r*512+c]
                            : ps.p[30][r] * ps.p[29][r*256+(c-512)];
        g_Wfin_h[i] = __float2half_rn(v);
        return;
    }
    i -= 196608;
    if (i < 2304) { g_wdw[i] = ps.p[27][i/9] * ps.p[26][i]; return; }
    i -= 2304;
    if (i < 32768) {
        int t = i >> 13, rest = i & 8191;
        int c = rest >> 6, n = rest & 63;
        float coord = 0.25f * (float)n - 0.375f;
        coord = fminf(fmaxf(coord, 0.0f), 15.0f);
        int lo = (int)floorf(coord);
        int hi = min(lo + 1, 15);
        float tf = coord - (float)lo;
        const float* src = ps.p[10 + t];
        g_pos[t][c*64 + n] = src[c*16+lo] * (1.0f - tf) + src[c*16+hi] * tf;
    }
}

// ---------------- axial attention (256 threads) ----------------
__global__ void attn_kernel() {
    int bid = blockIdx.x;
    int br = bid >> 7, b = (bid >> 3) & 15, h = bid & 7;
    __shared__ float qs[16][64], ks[16][64], vs[64][64], ps[64][65];
    __shared__ float red1[4][64], red2[4][64];
    int t = threadIdx.x;
    int n = t & 63, g = t >> 6;           // group 0..3
    for (int i = t; i < 1024; i += 256) {
        int kd = i >> 6, nn = i & 63;
        qs[kd][nn] = g_q[br][(h*16+kd)*1024 + b*64 + nn];
        ks[kd][nn] = g_k[br][(h*16+kd)*1024 + b*64 + nn];
    }
    for (int i = t; i < 4096; i += 256) {
        int d = i >> 6, nn = i & 63;
        vs[d][nn] = g_vax[br][(h*64+d)*1024 + b*64 + nn];
    }
    __syncthreads();
    float q[16];
    #pragma unroll
    for (int kd = 0; kd < 16; kd++) q[kd] = qs[kd][n];
    float mx = -1e30f;
    #pragma unroll
    for (int mm = 0; mm < 16; mm++) {
        int m = g * 16 + mm;
        float s = 0.f;
        #pragma unroll
        for (int kd = 0; kd < 16; kd++) s = fmaf(q[kd], ks[kd][m], s);
        s *= 0.25f;
        ps[n][m] = s;
        mx = fmaxf(mx, s);
    }
    red1[g][n] = mx;
    __syncthreads();
    float mxa = fmaxf(fmaxf(red1[0][n], red1[1][n]), fmaxf(red1[2][n], red1[3][n]));
    float sum = 0.f;
    #pragma unroll
    for (int mm = 0; mm < 16; mm++) {
        int m = g * 16 + mm;
        float e = __expf(ps[n][m] - mxa);
        ps[n][m] = e;
        sum += e;
    }
    red2[g][n] = sum;
    __syncthreads();
    float inv = 1.0f / (red2[0][n] + red2[1][n] + red2[2][n] + red2[3][n]);
    #pragma unroll
    for (int dd = 0; dd < 16; dd++) {
        int d = g * 16 + dd;
        float o = 0.f;
        #pragma unroll 8
        for (int m = 0; m < 64; m++) o = fmaf(ps[n][m], vs[d][m], o);
        g_ax[br][(h*64+d)*1024 + b*64 + n] = o * inv;
    }
}

// ---------------- depthwise (g1 fp16 in) -> g2 fp16 ----------------
__global__ void dw_kernel(const float* __restrict__ b_dw) {
    int bc = blockIdx.x;
    int c = bc & 255;
    __shared__ float sm[64][65];
    const __half* gp = &g_g1h[(size_t)bc * 4096];
    int t = threadIdx.x;
    for (int i = t; i < 4096; i += 256) sm[i >> 6][i & 63] = __half2float(gp[i]);
    __syncthreads();
    float w9[9];
    #pragma unroll
    for (int j = 0; j < 9; j++) w9[j] = g_wdw[c*9 + j];
    float bias = b_dw[c];
    for (int i = t; i < 4096; i += 256) {
        int h = i >> 6, w = i & 63;
        float s = 0.f;
        #pragma unroll
        for (int di = 0; di < 3; di++) {
            int hh = h + di - 1;
            if ((unsigned)hh >= 64u) continue;
            #pragma unroll
            for (int dj = 0; dj < 3; dj++) {
                int ww = w + dj - 1;
                if ((unsigned)ww >= 64u) continue;
                s = fmaf(sm[hh][ww], w9[di*3 + dj], s);
            }
        }
        g_g2b[(size_t)bc * 4096 + i] = __float2half_rn(fmaxf(s + bias, 0.0f));
    }
}

// ---------------- small SIMT GEMM (modes 0 & 2) ----------------
#define BM 128
#define BN 64
#define BK 16

__device__ __forceinline__ void rank1(float (&A)[8][4], float4 a0, float4 a1, float4 b) {
    float ar[8] = {a0.x, a0.y, a0.z, a0.w, a1.x, a1.y, a1.z, a1.w};
    #pragma unroll
    for (int r = 0; r < 8; r++) {
        A[r][0] = fmaf(ar[r], b.x, A[r][0]);
        A[r][1] = fmaf(ar[r], b.y, A[r][1]);
        A[r][2] = fmaf(ar[r], b.z, A[r][2]);
        A[r][3] = fmaf(ar[r], b.w, A[r][3]);
    }
}

template <int MODE>
__global__ void __launch_bounds__(256, 2) gemm_k(
        const float* __restrict__ b0, const float* __restrict__ b1,
        const float* __restrict__ b2) {
    constexpr int K = (MODE == 0) ? 256 : 512;
    __shared__ float As[BK][BM + 4];
    __shared__ float Bs[BK][BN + 4];
    const int tid = threadIdx.x;
    const int bx = blockIdx.x, by = blockIdx.y, bz = blockIdx.z;
    const int ty8 = (tid >> 4) << 3;
    const int tx4 = (tid & 15) << 2;
    const int m0 = by * BM;
    const int pt = bx * BN;
    const float* Wm = (MODE == 0) ? g_Wqkv : g_Wxx[bz];
    const int wml = tid >> 1;
    const int wkg = (tid & 1) * 8;
    const int xkk = tid >> 4;
    const int xpl = (tid & 15) << 2;

    float acc[8][4];
    #pragma unroll
    for (int r = 0; r < 8; r++)
        #pragma unroll
        for (int j = 0; j < 4; j++) acc[r][j] = 0.f;

    for (int kt = 0; kt < K; kt += BK) {
        const float* wp = &Wm[(m0 + wml) * K + kt + wkg];
        float4 w0 = *(const float4*)wp;
        float4 w1 = *(const float4*)(wp + 4);
        int k = kt + xkk;
        float4 xv;
        if (MODE == 0) {
            xv = *(const float4*)&g_xm[bz][k*1024 + pt + xpl];
        } else {
            float4 t4 = *(const float4*)&g_ax[bz][k*1024 + pt + xpl];
            xv.x = fmaxf(t4.x, 0.f); xv.y = fmaxf(t4.y, 0.f);
            xv.z = fmaxf(t4.z, 0.f); xv.w = fmaxf(t4.w, 0.f);
        }
        __syncthreads();
        As[wkg+0][wml] = w0.x; As[wkg+1][wml] = w0.y;
        As[wkg+2][wml] = w0.z; As[wkg+3][wml] = w0.w;
        As[wkg+4][wml] = w1.x; As[wkg+5][wml] = w1.y;
        As[wkg+6][wml] = w1.z; As[wkg+7][wml] = w1.w;
        *(float4*)&Bs[xkk][xpl] = xv;
        __syncthreads();
        #pragma unroll
        for (int u = 0; u < BK; u++) {
            float4 a0 = *(const float4*)&As[u][ty8];
            float4 a1 = *(const float4*)&As[u][ty8 + 4];
            float4 bv = *(const float4*)&Bs[u][tx4];
            rank1(acc, a0, a1, bv);
        }
    }

    #pragma unroll
    for (int r = 0; r < 8; r++) {
        int m = m0 + ty8 + r;
        if (MODE == 0) {
            float4 o;
            if (m < 128) {
                float4 pv = *(const float4*)&g_pos[bz ? 2 : 0][m*64 + tx4];
                float bb = b0[m];
                o.x = acc[r][0] + bb + pv.x; o.y = acc[r][1] + bb + pv.y;
                o.z = acc[r][2] + bb + pv.z; o.w = acc[r][3] + bb + pv.w;
                *(float4*)&g_q[bz][m*1024 + pt + tx4] = o;
            } else if (m < 256) {
                int mm = m - 128;
                float4 pv = *(const float4*)&g_pos[bz ? 3 : 1][mm*64 + tx4];
                float bb = b1[mm];
                o.x = acc[r][0] + bb + pv.x; o.y = acc[r][1] + bb + pv.y;
                o.z = acc[r][2] + bb + pv.z; o.w = acc[r][3] + bb + pv.w;
                *(float4*)&g_k[bz][mm*1024 + pt + tx4] = o;
            } else {
                int mm = m - 256;
                float bb = b2[mm];
                o.x = acc[r][0] + bb; o.y = acc[r][1] + bb;
                o.z = acc[r][2] + bb; o.w = acc[r][3] + bb;
                *(float4*)&g_vax[bz][mm*1024 + pt + tx4] = o;
            }
        } else {
            float bb = (bz ? b2 : b1)[m];
            float4 o;
            o.x = acc[r][0] + bb; o.y = acc[r][1] + bb;
            o.z = acc[r][2] + bb; o.w = acc[r][3] + bb;
            int bidx = pt >> 6;
            *(float4*)&g_xx[bz][(bidx*512 + m)*64 + tx4] = o;
        }
    }
}

// ---------------- HMMA GEMM (modes 1, 3, 4) ----------------
// CTA 256 thr, tile 128(ch) x 128(px); warps 4x2, warp tile 32x64.
// fp16 x fp16, fp32 acc. 3-stage cp.async pipeline, 1 sync/chunk.
// Stage layout: A 0 (128x72 halves, 144B stride) | B 18432 (64x136, 272B)
// Stage stride 35840 B; 3 stages (107.5KB; 2 CTA/SM).
#define MM_SMEM (3 * 35840)

template <int MODE>
__global__ void __launch_bounds__(256) mm_gemm(
        const float* __restrict__ bias0,
        const float* __restrict__ bias1,
        float* __restrict__ outp) {
    extern __shared__ char smem[];
    constexpr int K       = (MODE == 3) ? 512 : 256;
    constexpr int NC      = K / 64;
    constexpr int KSTRIDE = (MODE == 1) ? 256 : 768;
    constexpr int KOFF    = (MODE == 4) ? 512 : 0;
    constexpr int CH      = (MODE == 3) ? 512 : 256;
    const int tid = threadIdx.x, lane = tid & 31, wid = tid >> 5;
    const int wm = wid & 3, wn = wid >> 2;
    const int m0 = blockIdx.x * 128;
    const int pt = blockIdx.y;
    const int b_ = pt >> 5;
    const int hw0 = (pt & 31) << 7;

    const uint32_t sb = smem_u32(smem);
    const __half* Wh = (MODE == 1) ? g_Wvg1_h : g_Wfin_h;
    const __half* Bg = (MODE == 1) ? g_xh : (MODE == 3) ? g_pb : g_g2b;

    float acc[2][8][4];
    #pragma unroll
    for (int mf = 0; mf < 2; mf++)
        #pragma unroll
        for (int nf = 0; nf < 8; nf++)
            #pragma unroll
            for (int j = 0; j < 4; j++) acc[mf][nf][j] = 0.f;

    auto FILL = [&](int c) {
        const uint32_t st = sb + (uint32_t)(c % 3) * 35840u;
        const int kc = c * 64;
        #pragma unroll
        for (int i = 0; i < 4; i++) {          // A: 128x64 fp16
            int idx = tid + i * 256;
            int m = idx >> 3, k8 = (idx & 7) << 3;
            size_t g = (size_t)(m0 + m) * KSTRIDE + KOFF + kc + k8;
            CP16(st + (uint32_t)(m * 144 + k8 * 2), Wh + g);
        }
        #pragma unroll
        for (int i = 0; i < 4; i++) {          // B: 64k x 128px fp16
            int idx = tid + i * 256;
            int k = idx >> 4, px8 = (idx & 15) << 3;
            size_t g = (((size_t)(b_ * CH + kc + k)) << 12) + hw0 + px8;
            CP16(st + 18432u + (uint32_t)(k * 272 + px8 * 2), Bg + g);
        }
    };

    FILL(0); CP_COMMIT();
    FILL(1); CP_COMMIT();
    for (int c = 0; c < NC; c++) {
        if (c + 1 < NC) { CP_WAIT(1); } else { CP_WAIT(0); }
        __syncthreads();
        if (c + 2 < NC) { FILL(c + 2); CP_COMMIT(); }
        const uint32_t st = sb + (uint32_t)(c % 3) * 35840u;
        #pragma unroll
        for (int kk = 0; kk < 64; kk += 16) {
            uint32_t ah[2][4];
            uint32_t aoff = st + (uint32_t)(((wm * 32 + (lane & 15)) * 72
                              + kk + ((lane >> 4) << 3)) * 2);
            LDSM4(ah[0], aoff);
            LDSM4(ah[1], aoff + 16u * 144u);
            #pragma unroll
            for (int np = 0; np < 4; np++) {
                uint32_t bh[4];
                uint32_t boff = st + 18432u + (uint32_t)(
                    ((kk + (lane & 7) + (((lane >> 3) & 1) << 3)) * 136
                     + wn * 64 + np * 16 + ((lane >> 4) << 3)) * 2);
                LDSM4T(bh, boff);
                #pragma unroll
                for (int mf = 0; mf < 2; mf++) {
                    mma16816(acc[mf][2*np],   ah[mf], bh[0], bh[1]);
                    mma16816(acc[mf][2*np+1], ah[mf], bh[2], bh[3]);
                }
            }
        }
    }

    // ---- epilogue ----
    #pragma unroll
    for (int mf = 0; mf < 2; mf++) {
        int r0 = m0 + wm * 32 + mf * 16 + (lane >> 2);
        #pragma unroll
        for (int nf = 0; nf < 8; nf++) {
            int pxg = hw0 + wn * 64 + nf * 8 + ((lane & 3) << 1);
            #pragma unroll
            for (int half = 0; half < 2; half++) {
                int m = r0 + half * 8;
                float v0 = acc[mf][nf][half * 2 + 0];
                float v1 = acc[mf][nf][half * 2 + 1];
                if (MODE == 1) {
                    if (m < 512) {
                        float bb = bias0[m];
                        int hh = pxg >> 6, ww = pxg & 63;
                        float xr = g_xx[0][(b_*512 + m)*64 + hh];
                        float2 xc = *(const float2*)&g_xx[1][(b_*512 + m)*64 + ww];
                        float p0 = fmaxf(v0 + bb + xr + xc.x, 0.f);
                        float p1 = fmaxf(v1 + bb + xr + xc.y, 0.f);
                        size_t o = (((size_t)(b_*512 + m)) << 12) + pxg;
                        *(uint32_t*)&g_pb[o] = hpack(p0, p1);
                    } else {
                        float bb = bias1[m - 512];
                        size_t o = (((size_t)((b_ << 8) + m - 512)) << 12) + pxg;
                        *(uint32_t*)&g_g1h[o] = hpack(v0 + bb, v1 + bb);
                    }
                } else if (MODE == 4) {
                    float bb = bias0[m];
                    size_t o = (((size_t)((b_ << 8) + m)) << 12) + pxg;
                    *(uint32_t*)&g_gate[o] = hpack(hsig(v0 + bb), hsig(v1 + bb));
                } else {
                    float bb = bias0[m];
                    size_t o = (((size_t)((b_ << 8) + m)) << 12) + pxg;
                    uint32_t gv = *(const uint32_t*)&g_gate[o];
                    __half2 gh = *reinterpret_cast<__half2*>(&gv);
                    float2 g2 = __half22float2(gh);
                    float2 o2 = {(v0 + bb) * g2.x, (v1 + bb) * g2.y};
                    *(float2*)&outp[o] = o2;
                }
            }
        }
    }
}

// ---------------------------------------------------------------------------
extern "C" void kernel_launch(void* const* d_in, const int* in_sizes, int n_in,
                              void* d_out, int out_size) {
    (void)in_sizes; (void)n_in; (void)out_size;
    P32 ps;
    for (int i = 0; i < 32; i++) ps.p[i] = (const float*)d_in[i];
    const float* x      = ps.p[0];
    const float* bq     = ps.p[3];
    const float* bk     = ps.p[6];
    const float* bv     = ps.p[9];
    const float* b_row  = ps.p[16];
    const float* b_col  = ps.p[19];
    const float* b_proj = ps.p[22];
    const float* b_sc   = ps.p[25];
    const float* b_dw   = ps.p[28];
    const float* b_pw   = ps.p[31];
    float* out = (float*)d_out;

    cudaFuncSetAttribute(mm_gemm<1>, cudaFuncAttributeMaxDynamicSharedMemorySize, MM_SMEM);
    cudaFuncSetAttribute(mm_gemm<3>, cudaFuncAttributeMaxDynamicSharedMemorySize, MM_SMEM);
    cudaFuncSetAttribute(mm_gemm<4>, cudaFuncAttributeMaxDynamicSharedMemorySize, MM_SMEM);

    prep_reduce_kernel<<<8585, 256>>>(ps, x);
    gemm_k<0><<<dim3(16, 6, 2), 256>>>(bq, bk, bv);
    attn_kernel<<<256, 256>>>();
    gemm_k<2><<<dim3(16, 4, 2), 256>>>(nullptr, b_row, b_col);
    mm_gemm<1><<<dim3(6, 512), 256, MM_SMEM>>>(bv, b_sc, nullptr);
    dw_kernel<<<4096, 256>>>(b_dw);
    mm_gemm<4><<<dim3(2, 512), 256, MM_SMEM>>>(b_pw, nullptr, nullptr);
    mm_gemm<3><<<dim3(2, 512), 256, MM_SMEM>>>(b_proj, nullptr, out);
}

// round 14
// speedup vs baseline: 1.3956x; 1.1138x over previous
#include <cuda_runtime.h>
#include <cuda_bf16.h>
#include <cuda_fp16.h>
#include <math.h>
#include <stdint.h>

// ---------------------------------------------------------------------------
// Sea_Attention fused, round 14: axial GEMMs moved onto HMMA (modes 5/6);
// all five GEMMs now share the fp16 mm_gemm machinery.
//   prep_reduce -> mm<5>(qkv) -> attn -> mm<6>(xx) -> mm<1>(v,g1) -> dw
//   -> mm<4>(gate) -> mm<3>(proj*gate -> out)
// ---------------------------------------------------------------------------

#define BB 16

// ---------------- device scratch ----------------
__device__ __half g_Wqkv_h[768*256];
__device__ __half g_Wxx_h[2][512*512];
__device__ __half g_Wvg1_h[768*256];
__device__ __half g_Wfin_h[256*768];
__device__ float g_wdw[256*9];
__device__ float g_pos[4][128*64];
__device__ __half g_xmh[2][256*1024];
__device__ float g_q[2][128*1024];
__device__ float g_k[2][128*1024];
__device__ float g_vax[2][512*1024];
__device__ __half g_axh[2][512*1024];     // relu(attn out) fp16
__device__ float g_xx[2][BB*512*64];
// fp16 activation tensors
__device__ __half g_g1h[(size_t)BB*256*4096];
__device__ __half g_xh[(size_t)BB*256*4096];
__device__ __half g_pb[(size_t)BB*512*4096];
__device__ __half g_g2b[(size_t)BB*256*4096];
__device__ __half g_gate[(size_t)BB*256*4096];

struct P32 { const float* p[32]; };

__device__ __forceinline__ float hsig(float x) {
    return fminf(fmaxf(x + 3.0f, 0.0f), 6.0f) * (1.0f / 6.0f);
}

__device__ __forceinline__ uint32_t smem_u32(const void* p) {
    uint32_t a;
    asm("{ .reg .u64 t; cvta.to.shared.u64 t, %1; cvt.u32.u64 %0, t; }" : "=r"(a) : "l"(p));
    return a;
}

__device__ __forceinline__ void mma16816(float (&d)[4], const uint32_t (&a)[4],
                                         uint32_t b0, uint32_t b1) {
    asm volatile(
        "mma.sync.aligned.m16n8k16.row.col.f32.f16.f16.f32 "
        "{%0,%1,%2,%3}, {%4,%5,%6,%7}, {%8,%9}, {%0,%1,%2,%3};"
        : "+f"(d[0]), "+f"(d[1]), "+f"(d[2]), "+f"(d[3])
        : "r"(a[0]), "r"(a[1]), "r"(a[2]), "r"(a[3]), "r"(b0), "r"(b1));
}

#define LDSM4(r, a) asm volatile( \
    "ldmatrix.sync.aligned.m8n8.x4.shared.b16 {%0,%1,%2,%3}, [%4];" \
    : "=r"((r)[0]),"=r"((r)[1]),"=r"((r)[2]),"=r"((r)[3]) : "r"(a))
#define LDSM4T(r, a) asm volatile( \
    "ldmatrix.sync.aligned.m8n8.x4.trans.shared.b16 {%0,%1,%2,%3}, [%4];" \
    : "=r"((r)[0]),"=r"((r)[1]),"=r"((r)[2]),"=r"((r)[3]) : "r"(a))
#define CP16(d, s) asm volatile( \
    "cp.async.cg.shared.global [%0], [%1], 16;" :: "r"(d), "l"(s))
#define CP_COMMIT() asm volatile("cp.async.commit_group;")
#define CP_WAIT(n)  asm volatile("cp.async.wait_group %0;" :: "n"(n))

__device__ __forceinline__ uint32_t hpack(float a, float b) {
    __half2 t = __floats2half2_rn(a, b);
    return *reinterpret_cast<uint32_t*>(&t);
}

// ---------------- merged prep + reduce ----------------
// blocks [0, 4096): reduce (row/col means fp16 + x fp16)
// blocks [4096, 8585): prep (fold scales into fp16 weights, pos tables)
__global__ void prep_reduce_kernel(P32 ps, const float* __restrict__ x) {
    __shared__ float sm[64 * 65];
    if (blockIdx.x < 4096) {
        int bc = blockIdx.x;
        int b = bc >> 8, c = bc & 255;
        int t = threadIdx.x;
        const float* xp = x + (size_t)bc * 4096;
        for (int i = t; i < 4096; i += 256)
            sm[(i >> 6) * 65 + (i & 63)] = xp[i];
        __syncthreads();
        if (t < 64) {
            float s = 0.f;
            #pragma unroll
            for (int w = 0; w < 64; w++) s += sm[t*65 + w];
            g_xmh[0][c*1024 + b*64 + t] = __float2half_rn(s * (1.0f/64.0f));
        } else if (t < 128) {
            int w = t - 64;
            float s = 0.f;
            #pragma unroll
            for (int h = 0; h < 64; h++) s += sm[h*65 + w];
            g_xmh[1][c*1024 + b*64 + w] = __float2half_rn(s * (1.0f/64.0f));
        }
        for (int i = t; i < 4096; i += 256)
            g_xh[(size_t)bc * 4096 + i] = __float2half_rn(sm[(i >> 6) * 65 + (i & 63)]);
        return;
    }
    int i = (blockIdx.x - 4096) * 256 + threadIdx.x;
    if (i < 196608) {                       // Wqkv fp16
        int r = i >> 8, k = i & 255;
        float v;
        if (r < 128)      v = ps.p[2][r]     * ps.p[1][r*256+k];
        else if (r < 256) v = ps.p[5][r-128] * ps.p[4][(r-128)*256+k];
        else              v = ps.p[8][r-256] * ps.p[7][(r-256)*256+k];
        g_Wqkv_h[i] = __float2half_rn(v); return;
    }
    i -= 196608;
    if (i < 196608) {                       // Wvg1 fp16
        int r = i >> 8, k = i & 255;
        float v = (r < 512) ? ps.p[8][r] * ps.p[7][r*256+k]
                            : ps.p[24][r-512] * ps.p[23][(r-512)*256+k];
        g_Wvg1_h[i] = __float2half_rn(v);
        return;
    }
    i -= 196608;
    if (i < 262144) { int r = i >> 9; g_Wxx_h[0][i] = __float2half_rn(ps.p[15][r] * ps.p[14][i]); return; }
    i -= 262144;
    if (i < 262144) { int r = i >> 9; g_Wxx_h[1][i] = __float2half_rn(ps.p[18][r] * ps.p[17][i]); return; }
    i -= 262144;
    if (i < 196608) {                       // Wfin fp16
        int r = i / 768, c = i % 768;
        float v = (c < 512) ? ps.p[21][r] * ps.p[20][r*512+c]
                            : ps.p[30][r] * ps.p[29][r*256+(c-512)];
        g_Wfin_h[i] = __float2half_rn(v);
        return;
    }
    i -= 196608;
    if (i < 2304) { g_wdw[i] = ps.p[27][i/9] * ps.p[26][i]; return; }
    i -= 2304;
    if (i < 32768) {
        int t = i >> 13, rest = i & 8191;
        int c = rest >> 6, n = rest & 63;
        float coord = 0.25f * (float)n - 0.375f;
        coord = fminf(fmaxf(coord, 0.0f), 15.0f);
        int lo = (int)floorf(coord);
        int hi = min(lo + 1, 15);
        float tf = coord - (float)lo;
        const float* src = ps.p[10 + t];
        g_pos[t][c*64 + n] = src[c*16+lo] * (1.0f - tf) + src[c*16+hi] * tf;
    }
}

// ---------------- axial attention (256 threads) ----------------
__global__ void attn_kernel() {
    int bid = blockIdx.x;
    int br = bid >> 7, b = (bid >> 3) & 15, h = bid & 7;
    __shared__ float qs[16][64], ks[16][64], vs[64][64], ps[64][65];
    __shared__ float red1[4][64], red2[4][64];
    int t = threadIdx.x;
    int n = t & 63, g = t >> 6;
    for (int i = t; i < 1024; i += 256) {
        int kd = i >> 6, nn = i & 63;
        qs[kd][nn] = g_q[br][(h*16+kd)*1024 + b*64 + nn];
        ks[kd][nn] = g_k[br][(h*16+kd)*1024 + b*64 + nn];
    }
    for (int i = t; i < 4096; i += 256) {
        int d = i >> 6, nn = i & 63;
        vs[d][nn] = g_vax[br][(h*64+d)*1024 + b*64 + nn];
    }
    __syncthreads();
    float q[16];
    #pragma unroll
    for (int kd = 0; kd < 16; kd++) q[kd] = qs[kd][n];
    float mx = -1e30f;
    #pragma unroll
    for (int mm = 0; mm < 16; mm++) {
        int m = g * 16 + mm;
        float s = 0.f;
        #pragma unroll
        for (int kd = 0; kd < 16; kd++) s = fmaf(q[kd], ks[kd][m], s);
        s *= 0.25f;
        ps[n][m] = s;
        mx = fmaxf(mx, s);
    }
    red1[g][n] = mx;
    __syncthreads();
    float mxa = fmaxf(fmaxf(red1[0][n], red1[1][n]), fmaxf(red1[2][n], red1[3][n]));
    float sum = 0.f;
    #pragma unroll
    for (int mm = 0; mm < 16; mm++) {
        int m = g * 16 + mm;
        float e = __expf(ps[n][m] - mxa);
        ps[n][m] = e;
        sum += e;
    }
    red2[g][n] = sum;
    __syncthreads();
    float inv = 1.0f / (red2[0][n] + red2[1][n] + red2[2][n] + red2[3][n]);
    #pragma unroll
    for (int dd = 0; dd < 16; dd++) {
        int d = g * 16 + dd;
        float o = 0.f;
        #pragma unroll 8
        for (int m = 0; m < 64; m++) o = fmaf(ps[n][m], vs[d][m], o);
        // store relu'ed fp16 (consumer mode-6 needs relu(xx))
        g_axh[br][(h*64+d)*1024 + b*64 + n] = __float2half_rn(fmaxf(o * inv, 0.0f));
    }
}

// ---------------- depthwise (g1 fp16 in) -> g2 fp16 ----------------
__global__ void dw_kernel(const float* __restrict__ b_dw) {
    int bc = blockIdx.x;
    int c = bc & 255;
    __shared__ float sm[64][65];
    const __half* gp = &g_g1h[(size_t)bc * 4096];
    int t = threadIdx.x;
    for (int i = t; i < 4096; i += 256) sm[i >> 6][i & 63] = __half2float(gp[i]);
    __syncthreads();
    float w9[9];
    #pragma unroll
    for (int j = 0; j < 9; j++) w9[j] = g_wdw[c*9 + j];
    float bias = b_dw[c];
    for (int i = t; i < 4096; i += 256) {
        int h = i >> 6, w = i & 63;
        float s = 0.f;
        #pragma unroll
        for (int di = 0; di < 3; di++) {
            int hh = h + di - 1;
            if ((unsigned)hh >= 64u) continue;
            #pragma unroll
            for (int dj = 0; dj < 3; dj++) {
                int ww = w + dj - 1;
                if ((unsigned)ww >= 64u) continue;
                s = fmaf(sm[hh][ww], w9[di*3 + dj], s);
            }
        }
        g_g2b[(size_t)bc * 4096 + i] = __float2half_rn(fmaxf(s + bias, 0.0f));
    }
}

// ---------------- HMMA GEMM (all modes) ----------------
// CTA 256 thr, tile 128(ch) x 128(px); warps 4x2, warp tile 32x64.
// fp16 x fp16, fp32 acc. 3-stage cp.async pipeline.
// Stage: A 0 (128x72 halves, 144B stride) | B 18432 (64x136, 272B); 35840B.
// MODE 1: W=Wvg1 (K=256), B=xh   -> p fp16 / g1 fp16
// MODE 3: W=Wfin[:,0:512] (K=512), B=pb -> out = (proj+b)*gate
// MODE 4: W=Wfin[:,512:768] (K=256), B=g2 -> gate fp16
// MODE 5: W=Wqkv (K=256), B=xmh[z] -> q/k (+pos+bias) / vax (+bias) fp32
// MODE 6: W=Wxx[z] (K=512), B=axh[z] -> xx fp32 (+bias)
#define MM_SMEM (3 * 35840)

template <int MODE>
__global__ void __launch_bounds__(256) mm_gemm(
        const float* __restrict__ bias0,
        const float* __restrict__ bias1,
        const float* __restrict__ bias2,
        float* __restrict__ outp) {
    extern __shared__ char smem[];
    constexpr int K       = (MODE == 3 || MODE == 6) ? 512 : 256;
    constexpr int NC      = K / 64;
    constexpr int KSTRIDE = (MODE == 1 || MODE == 5) ? 256 : (MODE == 6) ? 512 : 768;
    constexpr int KOFF    = (MODE == 4) ? 512 : 0;
    constexpr int CH      = (MODE == 3) ? 512 : 256;
    constexpr bool AX     = (MODE == 5 || MODE == 6);
    const int tid = threadIdx.x, lane = tid & 31, wid = tid >> 5;
    const int wm = wid & 3, wn = wid >> 2;
    const int m0 = blockIdx.x * 128;
    const int pt = blockIdx.y;
    const int bz = AX ? blockIdx.z : 0;
    const int b_ = AX ? 0 : (pt >> 5);
    const int hw0 = AX ? (pt << 7) : ((pt & 31) << 7);

    const uint32_t sb = smem_u32(smem);
    const __half* Wh = (MODE == 1) ? g_Wvg1_h
                     : (MODE == 5) ? g_Wqkv_h
                     : (MODE == 6) ? g_Wxx_h[bz] : g_Wfin_h;
    const __half* Bg = (MODE == 1) ? g_xh
                     : (MODE == 3) ? g_pb
                     : (MODE == 4) ? g_g2b
                     : (MODE == 5) ? g_xmh[bz] : g_axh[bz];

    float acc[2][8][4];
    #pragma unroll
    for (int mf = 0; mf < 2; mf++)
        #pragma unroll
        for (int nf = 0; nf < 8; nf++)
            #pragma unroll
            for (int j = 0; j < 4; j++) acc[mf][nf][j] = 0.f;

    auto FILL = [&](int c) {
        const uint32_t st = sb + (uint32_t)(c % 3) * 35840u;
        const int kc = c * 64;
        #pragma unroll
        for (int i = 0; i < 4; i++) {          // A: 128x64 fp16
            int idx = tid + i * 256;
            int m = idx >> 3, k8 = (idx & 7) << 3;
            size_t g = (size_t)(m0 + m) * KSTRIDE + KOFF + kc + k8;
            CP16(st + (uint32_t)(m * 144 + k8 * 2), Wh + g);
        }
        #pragma unroll
        for (int i = 0; i < 4; i++) {          // B: 64k x 128px fp16
            int idx = tid + i * 256;
            int k = idx >> 4, px8 = (idx & 15) << 3;
            size_t g = AX ? ((size_t)(kc + k) * 1024 + hw0 + px8)
                          : ((((size_t)(b_ * CH + kc + k)) << 12) + hw0 + px8);
            CP16(st + 18432u + (uint32_t)(k * 272 + px8 * 2), Bg + g);
        }
    };

    FILL(0); CP_COMMIT();
    FILL(1); CP_COMMIT();
    for (int c = 0; c < NC; c++) {
        if (c + 1 < NC) { CP_WAIT(1); } else { CP_WAIT(0); }
        __syncthreads();
        if (c + 2 < NC) { FILL(c + 2); CP_COMMIT(); }
        const uint32_t st = sb + (uint32_t)(c % 3) * 35840u;
        #pragma unroll
        for (int kk = 0; kk < 64; kk += 16) {
            uint32_t ah[2][4];
            uint32_t aoff = st + (uint32_t)(((wm * 32 + (lane & 15)) * 72
                              + kk + ((lane >> 4) << 3)) * 2);
            LDSM4(ah[0], aoff);
            LDSM4(ah[1], aoff + 16u * 144u);
            #pragma unroll
            for (int np = 0; np < 4; np++) {
                uint32_t bh[4];
                uint32_t boff = st + 18432u + (uint32_t)(
                    ((kk + (lane & 7) + (((lane >> 3) & 1) << 3)) * 136
                     + wn * 64 + np * 16 + ((lane >> 4) << 3)) * 2);
                LDSM4T(bh, boff);
                #pragma unroll
                for (int mf = 0; mf < 2; mf++) {
                    mma16816(acc[mf][2*np],   ah[mf], bh[0], bh[1]);
                    mma16816(acc[mf][2*np+1], ah[mf], bh[2], bh[3]);
                }
            }
        }
    }

    // ---- epilogue ----
    #pragma unroll
    for (int mf = 0; mf < 2; mf++) {
        int r0 = m0 + wm * 32 + mf * 16 + (lane >> 2);
        #pragma unroll
        for (int nf = 0; nf < 8; nf++) {
            int pxg = hw0 + wn * 64 + nf * 8 + ((lane & 3) << 1);
            #pragma unroll
            for (int half = 0; half < 2; half++) {
                int m = r0 + half * 8;
                float v0 = acc[mf][nf][half * 2 + 0];
                float v1 = acc[mf][nf][half * 2 + 1];
                if (MODE == 1) {
                    if (m < 512) {
                        float bb = bias0[m];
                        int hh = pxg >> 6, ww = pxg & 63;
                        float xr = g_xx[0][(b_*512 + m)*64 + hh];
                        float2 xc = *(const float2*)&g_xx[1][(b_*512 + m)*64 + ww];
                        float p0 = fmaxf(v0 + bb + xr + xc.x, 0.f);
                        float p1 = fmaxf(v1 + bb + xr + xc.y, 0.f);
                        size_t o = (((size_t)(b_*512 + m)) << 12) + pxg;
                        *(uint32_t*)&g_pb[o] = hpack(p0, p1);
                    } else {
                        float bb = bias1[m - 512];
                        size_t o = (((size_t)((b_ << 8) + m - 512)) << 12) + pxg;
                        *(uint32_t*)&g_g1h[o] = hpack(v0 + bb, v1 + bb);
                    }
                } else if (MODE == 4) {
                    float bb = bias0[m];
                    size_t o = (((size_t)((b_ << 8) + m)) << 12) + pxg;
                    *(uint32_t*)&g_gate[o] = hpack(hsig(v0 + bb), hsig(v1 + bb));
                } else if (MODE == 3) {
                    float bb = bias0[m];
                    size_t o = (((size_t)((b_ << 8) + m)) << 12) + pxg;
                    uint32_t gv = *(const uint32_t*)&g_gate[o];
                    __half2 gh = *reinterpret_cast<__half2*>(&gv);
                    float2 g2 = __half22float2(gh);
                    float2 o2 = {(v0 + bb) * g2.x, (v1 + bb) * g2.y};
                    *(float2*)&outp[o] = o2;
                } else if (MODE == 5) {
                    int nn = pxg & 63;
                    float2 o2;
                    if (m < 128) {
                        float2 pv = *(const float2*)&g_pos[bz ? 2 : 0][m*64 + nn];
                        float bb = bias0[m];
                        o2.x = v0 + bb + pv.x; o2.y = v1 + bb + pv.y;
                        *(float2*)&g_q[bz][m*1024 + pxg] = o2;
                    } else if (m < 256) {
                        int mm = m - 128;
                        float2 pv = *(const float2*)&g_pos[bz ? 3 : 1][mm*64 + nn];
                        float bb = bias1[mm];
                        o2.x = v0 + bb + pv.x; o2.y = v1 + bb + pv.y;
                        *(float2*)&g_k[bz][mm*1024 + pxg] = o2;
                    } else {
                        int mm = m - 256;
                        float bb = bias2[mm];
                        o2.x = v0 + bb; o2.y = v1 + bb;
                        *(float2*)&g_vax[bz][mm*1024 + pxg] = o2;
                    }
                } else {  // MODE 6
                    int bb_ = pxg >> 6, nn = pxg & 63;
                    float bb = (bz ? bias1 : bias0)[m];
                    float2 o2 = {v0 + bb, v1 + bb};
                    *(float2*)&g_xx[bz][(bb_*512 + m)*64 + nn] = o2;
                }
            }
        }
    }
}

// ---------------------------------------------------------------------------
extern "C" void kernel_launch(void* const* d_in, const int* in_sizes, int n_in,
                              void* d_out, int out_size) {
    (void)in_sizes; (void)n_in; (void)out_size;
    P32 ps;
    for (int i = 0; i < 32; i++) ps.p[i] = (const float*)d_in[i];
    const float* x      = ps.p[0];
    const float* bq     = ps.p[3];
    const float* bk     = ps.p[6];
    const float* bv     = ps.p[9];
    const float* b_row  = ps.p[16];
    const float* b_col  = ps.p[19];
    const float* b_proj = ps.p[22];
    const float* b_sc   = ps.p[25];
    const float* b_dw   = ps.p[28];
    const float* b_pw   = ps.p[31];
    float* out = (float*)d_out;

    cudaFuncSetAttribute(mm_gemm<1>, cudaFuncAttributeMaxDynamicSharedMemorySize, MM_SMEM);
    cudaFuncSetAttribute(mm_gemm<3>, cudaFuncAttributeMaxDynamicSharedMemorySize, MM_SMEM);
    cudaFuncSetAttribute(mm_gemm<4>, cudaFuncAttributeMaxDynamicSharedMemorySize, MM_SMEM);
    cudaFuncSetAttribute(mm_gemm<5>, cudaFuncAttributeMaxDynamicSharedMemorySize, MM_SMEM);
    cudaFuncSetAttribute(mm_gemm<6>, cudaFuncAttributeMaxDynamicSharedMemorySize, MM_SMEM);

    prep_reduce_kernel<<<8585, 256>>>(ps, x);
    mm_gemm<5><<<dim3(6, 8, 2), 256, MM_SMEM>>>(bq, bk, bv, nullptr);
    attn_kernel<<<256, 256>>>();
    mm_gemm<6><<<dim3(4, 8, 2), 256, MM_SMEM>>>(b_row, b_col, nullptr, nullptr);
    mm_gemm<1><<<dim3(6, 512), 256, MM_SMEM>>>(bv, b_sc, nullptr, nullptr);
    dw_kernel<<<4096, 256>>>(b_dw);
    mm_gemm<4><<<dim3(2, 512), 256, MM_SMEM>>>(b_pw, nullptr, nullptr, nullptr);
    mm_gemm<3><<<dim3(2, 512), 256, MM_SMEM>>>(b_proj, nullptr, nullptr, out);
}

// round 15
// speedup vs baseline: 1.4865x; 1.0651x over previous
#include <cuda_runtime.h>
#include <cuda_bf16.h>
#include <cuda_fp16.h>
#include <math.h>
#include <stdint.h>

// ---------------------------------------------------------------------------
// Sea_Attention fused, round 15:
//  - BM=64 tile variant for small-M GEMMs (modes 5/6) -> full-chip grids
//  - mode 7: fused proj+pw dual-accumulator GEMM (K=768), fp32 gate epilogue
//   prep_reduce -> mm<5>(qkv) -> attn -> mm<6>(xx) -> mm<1>(v,g1) -> dw
//   -> mm<7>(out = (proj+b)*hsig(pw+b))
// ---------------------------------------------------------------------------

#define BB 16

// ---------------- device scratch ----------------
__device__ __half g_Wqkv_h[768*256];
__device__ __half g_Wxx_h[2][512*512];
__device__ __half g_Wvg1_h[768*256];
__device__ __half g_Wfin_h[256*768];
__device__ float g_wdw[256*9];
__device__ float g_pos[4][128*64];
__device__ __half g_xmh[2][256*1024];
__device__ float g_q[2][128*1024];
__device__ float g_k[2][128*1024];
__device__ float g_vax[2][512*1024];
__device__ __half g_axh[2][512*1024];     // relu(attn out) fp16
__device__ float g_xx[2][BB*512*64];
// fp16 activation tensors
__device__ __half g_g1h[(size_t)BB*256*4096];
__device__ __half g_xh[(size_t)BB*256*4096];
__device__ __half g_pb[(size_t)BB*512*4096];
__device__ __half g_g2b[(size_t)BB*256*4096];

struct P32 { const float* p[32]; };

__device__ __forceinline__ float hsig(float x) {
    return fminf(fmaxf(x + 3.0f, 0.0f), 6.0f) * (1.0f / 6.0f);
}

__device__ __forceinline__ uint32_t smem_u32(const void* p) {
    uint32_t a;
    asm("{ .reg .u64 t; cvta.to.shared.u64 t, %1; cvt.u32.u64 %0, t; }" : "=r"(a) : "l"(p));
    return a;
}

__device__ __forceinline__ void mma16816(float (&d)[4], const uint32_t (&a)[4],
                                         uint32_t b0, uint32_t b1) {
    asm volatile(
        "mma.sync.aligned.m16n8k16.row.col.f32.f16.f16.f32 "
        "{%0,%1,%2,%3}, {%4,%5,%6,%7}, {%8,%9}, {%0,%1,%2,%3};"
        : "+f"(d[0]), "+f"(d[1]), "+f"(d[2]), "+f"(d[3])
        : "r"(a[0]), "r"(a[1]), "r"(a[2]), "r"(a[3]), "r"(b0), "r"(b1));
}

#define LDSM4(r, a) asm volatile( \
    "ldmatrix.sync.aligned.m8n8.x4.shared.b16 {%0,%1,%2,%3}, [%4];" \
    : "=r"((r)[0]),"=r"((r)[1]),"=r"((r)[2]),"=r"((r)[3]) : "r"(a))
#define LDSM4T(r, a) asm volatile( \
    "ldmatrix.sync.aligned.m8n8.x4.trans.shared.b16 {%0,%1,%2,%3}, [%4];" \
    : "=r"((r)[0]),"=r"((r)[1]),"=r"((r)[2]),"=r"((r)[3]) : "r"(a))
#define CP16(d, s) asm volatile( \
    "cp.async.cg.shared.global [%0], [%1], 16;" :: "r"(d), "l"(s))
#define CP_COMMIT() asm volatile("cp.async.commit_group;")
#define CP_WAIT(n)  asm volatile("cp.async.wait_group %0;" :: "n"(n))

__device__ __forceinline__ uint32_t hpack(float a, float b) {
    __half2 t = __floats2half2_rn(a, b);
    return *reinterpret_cast<uint32_t*>(&t);
}

// ---------------- merged prep + reduce ----------------
__global__ void prep_reduce_kernel(P32 ps, const float* __restrict__ x) {
    __shared__ float sm[64 * 65];
    if (blockIdx.x < 4096) {
        int bc = blockIdx.x;
        int b = bc >> 8, c = bc & 255;
        int t = threadIdx.x;
        const float* xp = x + (size_t)bc * 4096;
        for (int i = t; i < 4096; i += 256)
            sm[(i >> 6) * 65 + (i & 63)] = xp[i];
        __syncthreads();
        if (t < 64) {
            float s = 0.f;
            #pragma unroll
            for (int w = 0; w < 64; w++) s += sm[t*65 + w];
            g_xmh[0][c*1024 + b*64 + t] = __float2half_rn(s * (1.0f/64.0f));
        } else if (t < 128) {
            int w = t - 64;
            float s = 0.f;
            #pragma unroll
            for (int h = 0; h < 64; h++) s += sm[h*65 + w];
            g_xmh[1][c*1024 + b*64 + w] = __float2half_rn(s * (1.0f/64.0f));
        }
        for (int i = t; i < 4096; i += 256)
            g_xh[(size_t)bc * 4096 + i] = __float2half_rn(sm[(i >> 6) * 65 + (i & 63)]);
        return;
    }
    int i = (blockIdx.x - 4096) * 256 + threadIdx.x;
    if (i < 196608) {                       // Wqkv fp16
        int r = i >> 8, k = i & 255;
        float v;
        if (r < 128)      v = ps.p[2][r]     * ps.p[1][r*256+k];
        else if (r < 256) v = ps.p[5][r-128] * ps.p[4][(r-128)*256+k];
        else              v = ps.p[8][r-256] * ps.p[7][(r-256)*256+k];
        g_Wqkv_h[i] = __float2half_rn(v); return;
    }
    i -= 196608;
    if (i < 196608) {                       // Wvg1 fp16
        int r = i >> 8, k = i & 255;
        float v = (r < 512) ? ps.p[8][r] * ps.p[7][r*256+k]
                            : ps.p[24][r-512] * ps.p[23][(r-512)*256+k];
        g_Wvg1_h[i] = __float2half_rn(v);
        return;
    }
    i -= 196608;
    if (i < 262144) { int r = i >> 9; g_Wxx_h[0][i] = __float2half_rn(ps.p[15][r] * ps.p[14][i]); return; }
    i -= 262144;
    if (i < 262144) { int r = i >> 9; g_Wxx_h[1][i] = __float2half_rn(ps.p[18][r] * ps.p[17][i]); return; }
    i -= 262144;
    if (i < 196608) {                       // Wfin fp16
        int r = i / 768, c = i % 768;
        float v = (c < 512) ? ps.p[21][r] * ps.p[20][r*512+c]
                            : ps.p[30][r] * ps.p[29][r*256+(c-512)];
        g_Wfin_h[i] = __float2half_rn(v);
        return;
    }
    i -= 196608;
    if (i < 2304) { g_wdw[i] = ps.p[27][i/9] * ps.p[26][i]; return; }
    i -= 2304;
    if (i < 32768) {
        int t = i >> 13, rest = i & 8191;
        int c = rest >> 6, n = rest & 63;
        float coord = 0.25f * (float)n - 0.375f;
        coord = fminf(fmaxf(coord, 0.0f), 15.0f);
        int lo = (int)floorf(coord);
        int hi = min(lo + 1, 15);
        float tf = coord - (float)lo;
        const float* src = ps.p[10 + t];
        g_pos[t][c*64 + n] = src[c*16+lo] * (1.0f - tf) + src[c*16+hi] * tf;
    }
}

// ---------------- axial attention (256 threads) ----------------
__global__ void attn_kernel() {
    int bid = blockIdx.x;
    int br = bid >> 7, b = (bid >> 3) & 15, h = bid & 7;
    __shared__ float qs[16][64], ks[16][64], vs[64][64], ps[64][65];
    __shared__ float red1[4][64], red2[4][64];
    int t = threadIdx.x;
    int n = t & 63, g = t >> 6;
    for (int i = t; i < 1024; i += 256) {
        int kd = i >> 6, nn = i & 63;
        qs[kd][nn] = g_q[br][(h*16+kd)*1024 + b*64 + nn];
        ks[kd][nn] = g_k[br][(h*16+kd)*1024 + b*64 + nn];
    }
    for (int i = t; i < 4096; i += 256) {
        int d = i >> 6, nn = i & 63;
        vs[d][nn] = g_vax[br][(h*64+d)*1024 + b*64 + nn];
    }
    __syncthreads();
    float q[16];
    #pragma unroll
    for (int kd = 0; kd < 16; kd++) q[kd] = qs[kd][n];
    float mx = -1e30f;
    #pragma unroll
    for (int mm = 0; mm < 16; mm++) {
        int m = g * 16 + mm;
        float s = 0.f;
        #pragma unroll
        for (int kd = 0; kd < 16; kd++) s = fmaf(q[kd], ks[kd][m], s);
        s *= 0.25f;
        ps[n][m] = s;
        mx = fmaxf(mx, s);
    }
    red1[g][n] = mx;
    __syncthreads();
    float mxa = fmaxf(fmaxf(red1[0][n], red1[1][n]), fmaxf(red1[2][n], red1[3][n]));
    float sum = 0.f;
    #pragma unroll
    for (int mm = 0; mm < 16; mm++) {
        int m = g * 16 + mm;
        float e = __expf(ps[n][m] - mxa);
        ps[n][m] = e;
        sum += e;
    }
    red2[g][n] = sum;
    __syncthreads();
    float inv = 1.0f / (red2[0][n] + red2[1][n] + red2[2][n] + red2[3][n]);
    #pragma unroll
    for (int dd = 0; dd < 16; dd++) {
        int d = g * 16 + dd;
        float o = 0.f;
        #pragma unroll 8
        for (int m = 0; m < 64; m++) o = fmaf(ps[n][m], vs[d][m], o);
        g_axh[br][(h*64+d)*1024 + b*64 + n] = __float2half_rn(fmaxf(o * inv, 0.0f));
    }
}

// ---------------- depthwise (g1 fp16 in) -> g2 fp16 ----------------
__global__ void dw_kernel(const float* __restrict__ b_dw) {
    int bc = blockIdx.x;
    int c = bc & 255;
    __shared__ float sm[64][65];
    const __half* gp = &g_g1h[(size_t)bc * 4096];
    int t = threadIdx.x;
    for (int i = t; i < 4096; i += 256) sm[i >> 6][i & 63] = __half2float(gp[i]);
    __syncthreads();
    float w9[9];
    #pragma unroll
    for (int j = 0; j < 9; j++) w9[j] = g_wdw[c*9 + j];
    float bias = b_dw[c];
    for (int i = t; i < 4096; i += 256) {
        int h = i >> 6, w = i & 63;
        float s = 0.f;
        #pragma unroll
        for (int di = 0; di < 3; di++) {
            int hh = h + di - 1;
            if ((unsigned)hh >= 64u) continue;
            #pragma unroll
            for (int dj = 0; dj < 3; dj++) {
                int ww = w + dj - 1;
                if ((unsigned)ww >= 64u) continue;
                s = fmaf(sm[hh][ww], w9[di*3 + dj], s);
            }
        }
        g_g2b[(size_t)bc * 4096 + i] = __float2half_rn(fmaxf(s + bias, 0.0f));
    }
}

// ---------------- HMMA GEMM (modes 1, 5, 6, 7) ----------------
// CTA 256 thr. BMt=128 (mode 1): warps 4(m)x2(n), warp 32x64.
//              BMt=64 (modes 5,6,7): warps 2(m)x4(n), warp 32x32.
// fp16 x fp16, fp32 acc. 3-stage cp.async pipeline.
// Stage: A [BMt x 72 halves, 144B stride] | B [64 x 136 halves, 272B stride].
// MODE 1: W=Wvg1 (K=256), B=xh   -> p fp16 (relu(v+xx)) / g1 fp16
// MODE 5: W=Wqkv (K=256), B=xmh[z] -> q/k (+pos+bias) / vax (+bias) fp32
// MODE 6: W=Wxx[z] (K=512), B=axh[z] -> xx fp32 (+bias)
// MODE 7: W=Wfin (K=768): c<8 -> accP (B=pb), c>=8 -> accG (B=g2b);
//         out = (accP + b_proj) * hsig(accG + b_pw)
#define MM_SMEM128 (3 * 35840)
#define MM_SMEM64  (3 * 26624)

template <int MODE>
__global__ void __launch_bounds__(256) mm_gemm(
        const float* __restrict__ bias0,
        const float* __restrict__ bias1,
        const float* __restrict__ bias2,
        float* __restrict__ outp) {
    extern __shared__ char smem[];
    constexpr int K       = (MODE == 6) ? 512 : (MODE == 7) ? 768 : 256;
    constexpr int NC      = K / 64;
    constexpr int NCP     = (MODE == 7) ? 8 : NC;     // chunks into accP
    constexpr int KSTRIDE = K;                         // all weights K-contig
    constexpr bool AX     = (MODE == 5 || MODE == 6);
    constexpr int BMt     = (MODE == 1) ? 128 : 64;
    constexpr int WMC     = BMt / 32;                  // warp rows
    constexpr int NP      = WMC;                       // 16px groups per warp
    constexpr uint32_t BOFF = BMt * 144;
    constexpr uint32_t STG  = BMt * 144 + 17408;
    const int tid = threadIdx.x, lane = tid & 31, wid = tid >> 5;
    const int wm = wid % WMC, wn = wid / WMC;
    const int m0 = blockIdx.x * BMt;
    const int pt = blockIdx.y;
    const int bz = AX ? blockIdx.z : 0;
    const int b_ = AX ? 0 : (pt >> 5);
    const int hw0 = AX ? (pt << 7) : ((pt & 31) << 7);

    const uint32_t sb = smem_u32(smem);
    const __half* Wh = (MODE == 1) ? g_Wvg1_h
                     : (MODE == 5) ? g_Wqkv_h
                     : (MODE == 6) ? g_Wxx_h[bz] : g_Wfin_h;
    const __half* Bg = (MODE == 1) ? g_xh
                     : (MODE == 5) ? g_xmh[bz]
                     : (MODE == 6) ? g_axh[bz] : g_pb;

    float accP[2][2*NP][4], accG[2][2*NP][4];
    #pragma unroll
    for (int mf = 0; mf < 2; mf++)
        #pragma unroll
        for (int nf = 0; nf < 2*NP; nf++)
            #pragma unroll
            for (int j = 0; j < 4; j++) { accP[mf][nf][j] = 0.f; accG[mf][nf][j] = 0.f; }

    auto FILL = [&](int c) {
        const uint32_t st = sb + (uint32_t)(c % 3) * STG;
        const int kc = c * 64;
        #pragma unroll
        for (int i = 0; i < BMt/32; i++) {     // A: BMt x 64 fp16
            int idx = tid + i * 256;
            int m = idx >> 3, k8 = (idx & 7) << 3;
            size_t g = (size_t)(m0 + m) * KSTRIDE + kc + k8;
            CP16(st + (uint32_t)(m * 144 + k8 * 2), Wh + g);
        }
        #pragma unroll
        for (int i = 0; i < 4; i++) {          // B: 64k x 128px fp16
            int idx = tid + i * 256;
            int k = idx >> 4, px8 = (idx & 15) << 3;
            const __half* src;
            size_t g;
            if (MODE == 7) {
                int kch = kc + k;
                if (kch < 512) { src = g_pb;  g = (((size_t)(b_ * 512 + kch)) << 12) + hw0 + px8; }
                else           { src = g_g2b; g = (((size_t)(b_ * 256 + kch - 512)) << 12) + hw0 + px8; }
            } else if (AX) {
                src = Bg; g = (size_t)(kc + k) * 1024 + hw0 + px8;
            } else {
                src = Bg; g = (((size_t)(b_ * 256 + kc + k)) << 12) + hw0 + px8;
            }
            CP16(st + BOFF + (uint32_t)(k * 272 + px8 * 2), src + g);
        }
    };

#define MM_CHUNK(ACC) do { \
        if (c + 1 < NC) { CP_WAIT(1); } else { CP_WAIT(0); } \
        __syncthreads(); \
        if (c + 2 < NC) { FILL(c + 2); CP_COMMIT(); } \
        const uint32_t st = sb + (uint32_t)(c % 3) * STG; \
        _Pragma("unroll") \
        for (int kk = 0; kk < 64; kk += 16) { \
            uint32_t ah[2][4]; \
            uint32_t aoff = st + (uint32_t)(((wm * 32 + (lane & 15)) * 72 \
                              + kk + ((lane >> 4) << 3)) * 2); \
            LDSM4(ah[0], aoff); \
            LDSM4(ah[1], aoff + 2304u); \
            _Pragma("unroll") \
            for (int np = 0; np < NP; np++) { \
                uint32_t bh[4]; \
                uint32_t boff = st + BOFF + (uint32_t)( \
                    ((kk + (lane & 7) + (((lane >> 3) & 1) << 3)) * 136 \
                     + wn * (16*NP) + np * 16 + ((lane >> 4) << 3)) * 2); \
                LDSM4T(bh, boff); \
                _Pragma("unroll") \
                for (int mf = 0; mf < 2; mf++) { \
                    mma16816(ACC[mf][2*np],   ah[mf], bh[0], bh[1]); \
                    mma16816(ACC[mf][2*np+1], ah[mf], bh[2], bh[3]); \
                } \
            } \
        } \
    } while (0)

    FILL(0); CP_COMMIT();
    FILL(1); CP_COMMIT();
    for (int c = 0; c < NCP; c++) MM_CHUNK(accP);
    if (MODE == 7)
        for (int c = NCP; c < NC; c++) MM_CHUNK(accG);
#undef MM_CHUNK

    // ---- epilogue ----
    #pragma unroll
    for (int mf = 0; mf < 2; mf++) {
        int r0 = m0 + wm * 32 + mf * 16 + (lane >> 2);
        #pragma unroll
        for (int nf = 0; nf < 2*NP; nf++) {
            int pxg = hw0 + wn * (16*NP) + nf * 8 + ((lane & 3) << 1);
            #pragma unroll
            for (int half = 0; half < 2; half++) {
                int m = r0 + half * 8;
                float v0 = accP[mf][nf][half * 2 + 0];
                float v1 = accP[mf][nf][half * 2 + 1];
                if (MODE == 1) {
                    if (m < 512) {
                        float bb = bias0[m];
                        int hh = pxg >> 6, ww = pxg & 63;
                        float xr = g_xx[0][(b_*512 + m)*64 + hh];
                        float2 xc = *(const float2*)&g_xx[1][(b_*512 + m)*64 + ww];
                        float p0 = fmaxf(v0 + bb + xr + xc.x, 0.f);
                        float p1 = fmaxf(v1 + bb + xr + xc.y, 0.f);
                        size_t o = (((size_t)(b_*512 + m)) << 12) + pxg;
                        *(uint32_t*)&g_pb[o] = hpack(p0, p1);
                    } else {
                        float bb = bias1[m - 512];
                        size_t o = (((size_t)((b_ << 8) + m - 512)) << 12) + pxg;
                        *(uint32_t*)&g_g1h[o] = hpack(v0 + bb, v1 + bb);
                    }
                } else if (MODE == 7) {
                    float bp = bias0[m], bw = bias1[m];
                    float g0 = hsig(accG[mf][nf][half * 2 + 0] + bw);
                    float g1 = hsig(accG[mf][nf][half * 2 + 1] + bw);
                    size_t o = (((size_t)((b_ << 8) + m)) << 12) + pxg;
                    float2 o2 = {(v0 + bp) * g0, (v1 + bp) * g1};
                    *(float2*)&outp[o] = o2;
                } else if (MODE == 5) {
                    int nn = pxg & 63;
                    float2 o2;
                    if (m < 128) {
                        float2 pv = *(const float2*)&g_pos[bz ? 2 : 0][m*64 + nn];
                        float bb = bias0[m];
                        o2.x = v0 + bb + pv.x; o2.y = v1 + bb + pv.y;
                        *(float2*)&g_q[bz][m*1024 + pxg] = o2;
                    } else if (m < 256) {
                        int mm = m - 128;
                        float2 pv = *(const float2*)&g_pos[bz ? 3 : 1][mm*64 + nn];
                        float bb = bias1[mm];
                        o2.x = v0 + bb + pv.x; o2.y = v1 + bb + pv.y;
                        *(float2*)&g_k[bz][mm*1024 + pxg] = o2;
                    } else {
                        int mm = m - 256;
                        float bb = bias2[mm];
                        o2.x = v0 + bb; o2.y = v1 + bb;
                        *(float2*)&g_vax[bz][mm*1024 + pxg] = o2;
                    }
                } else {  // MODE 6
                    int bb_ = pxg >> 6, nn = pxg & 63;
                    float bb = (bz ? bias1 : bias0)[m];
                    float2 o2 = {v0 + bb, v1 + bb};
                    *(float2*)&g_xx[bz][(bb_*512 + m)*64 + nn] = o2;
                }
            }
        }
    }
}

// ---------------------------------------------------------------------------
extern "C" void kernel_launch(void* const* d_in, const int* in_sizes, int n_in,
                              void* d_out, int out_size) {
    (void)in_sizes; (void)n_in; (void)out_size;
    P32 ps;
    for (int i = 0; i < 32; i++) ps.p[i] = (const float*)d_in[i];
    const float* x      = ps.p[0];
    const float* bq     = ps.p[3];
    const float* bk     = ps.p[6];
    const float* bv     = ps.p[9];
    const float* b_row  = ps.p[16];
    const float* b_col  = ps.p[19];
    const float* b_proj = ps.p[22];
    const float* b_sc   = ps.p[25];
    const float* b_dw   = ps.p[28];
    const float* b_pw   = ps.p[31];
    float* out = (float*)d_out;

    cudaFuncSetAttribute(mm_gemm<1>, cudaFuncAttributeMaxDynamicSharedMemorySize, MM_SMEM128);
    cudaFuncSetAttribute(mm_gemm<5>, cudaFuncAttributeMaxDynamicSharedMemorySize, MM_SMEM64);
    cudaFuncSetAttribute(mm_gemm<6>, cudaFuncAttributeMaxDynamicSharedMemorySize, MM_SMEM64);
    cudaFuncSetAttribute(mm_gemm<7>, cudaFuncAttributeMaxDynamicSharedMemorySize, MM_SMEM64);

    prep_reduce_kernel<<<8585, 256>>>(ps, x);
    mm_gemm<5><<<dim3(12, 8, 2), 256, MM_SMEM64>>>(bq, bk, bv, nullptr);
    attn_kernel<<<256, 256>>>();
    mm_gemm<6><<<dim3(8, 8, 2), 256, MM_SMEM64>>>(b_row, b_col, nullptr, nullptr);
    mm_gemm<1><<<dim3(6, 512), 256, MM_SMEM128>>>(bv, b_sc, nullptr, nullptr);
    dw_kernel<<<4096, 256>>>(b_dw);
    mm_gemm<7><<<dim3(4, 512), 256, MM_SMEM64>>>(b_proj, b_pw, nullptr, out);
}

// round 16
// speedup vs baseline: 1.5225x; 1.0242x over previous
#include <cuda_runtime.h>
#include <cuda_bf16.h>
#include <cuda_fp16.h>
#include <math.h>
#include <stdint.h>

// ---------------------------------------------------------------------------
// Sea_Attention fused, round 16: dw_kernel rewritten (zero-padded tile,
// rolling-register 3-tap column strips, no boundary branches).
// Rest identical to round 15 (373.5 us).
// ---------------------------------------------------------------------------

#define BB 16

// ---------------- device scratch ----------------
__device__ __half g_Wqkv_h[768*256];
__device__ __half g_Wxx_h[2][512*512];
__device__ __half g_Wvg1_h[768*256];
__device__ __half g_Wfin_h[256*768];
__device__ float g_wdw[256*9];
__device__ float g_pos[4][128*64];
__device__ __half g_xmh[2][256*1024];
__device__ float g_q[2][128*1024];
__device__ float g_k[2][128*1024];
__device__ float g_vax[2][512*1024];
__device__ __half g_axh[2][512*1024];     // relu(attn out) fp16
__device__ float g_xx[2][BB*512*64];
// fp16 activation tensors
__device__ __half g_g1h[(size_t)BB*256*4096];
__device__ __half g_xh[(size_t)BB*256*4096];
__device__ __half g_pb[(size_t)BB*512*4096];
__device__ __half g_g2b[(size_t)BB*256*4096];

struct P32 { const float* p[32]; };

__device__ __forceinline__ float hsig(float x) {
    return fminf(fmaxf(x + 3.0f, 0.0f), 6.0f) * (1.0f / 6.0f);
}

__device__ __forceinline__ uint32_t smem_u32(const void* p) {
    uint32_t a;
    asm("{ .reg .u64 t; cvta.to.shared.u64 t, %1; cvt.u32.u64 %0, t; }" : "=r"(a) : "l"(p));
    return a;
}

__device__ __forceinline__ void mma16816(float (&d)[4], const uint32_t (&a)[4],
                                         uint32_t b0, uint32_t b1) {
    asm volatile(
        "mma.sync.aligned.m16n8k16.row.col.f32.f16.f16.f32 "
        "{%0,%1,%2,%3}, {%4,%5,%6,%7}, {%8,%9}, {%0,%1,%2,%3};"
        : "+f"(d[0]), "+f"(d[1]), "+f"(d[2]), "+f"(d[3])
        : "r"(a[0]), "r"(a[1]), "r"(a[2]), "r"(a[3]), "r"(b0), "r"(b1));
}

#define LDSM4(r, a) asm volatile( \
    "ldmatrix.sync.aligned.m8n8.x4.shared.b16 {%0,%1,%2,%3}, [%4];" \
    : "=r"((r)[0]),"=r"((r)[1]),"=r"((r)[2]),"=r"((r)[3]) : "r"(a))
#define LDSM4T(r, a) asm volatile( \
    "ldmatrix.sync.aligned.m8n8.x4.trans.shared.b16 {%0,%1,%2,%3}, [%4];" \
    : "=r"((r)[0]),"=r"((r)[1]),"=r"((r)[2]),"=r"((r)[3]) : "r"(a))
#define CP16(d, s) asm volatile( \
    "cp.async.cg.shared.global [%0], [%1], 16;" :: "r"(d), "l"(s))
#define CP_COMMIT() asm volatile("cp.async.commit_group;")
#define CP_WAIT(n)  asm volatile("cp.async.wait_group %0;" :: "n"(n))

__device__ __forceinline__ uint32_t hpack(float a, float b) {
    __half2 t = __floats2half2_rn(a, b);
    return *reinterpret_cast<uint32_t*>(&t);
}

// ---------------- merged prep + reduce ----------------
__global__ void prep_reduce_kernel(P32 ps, const float* __restrict__ x) {
    __shared__ float sm[64 * 65];
    if (blockIdx.x < 4096) {
        int bc = blockIdx.x;
        int b = bc >> 8, c = bc & 255;
        int t = threadIdx.x;
        const float* xp = x + (size_t)bc * 4096;
        for (int i = t; i < 4096; i += 256)
            sm[(i >> 6) * 65 + (i & 63)] = xp[i];
        __syncthreads();
        if (t < 64) {
            float s = 0.f;
            #pragma unroll
            for (int w = 0; w < 64; w++) s += sm[t*65 + w];
            g_xmh[0][c*1024 + b*64 + t] = __float2half_rn(s * (1.0f/64.0f));
        } else if (t < 128) {
            int w = t - 64;
            float s = 0.f;
            #pragma unroll
            for (int h = 0; h < 64; h++) s += sm[h*65 + w];
            g_xmh[1][c*1024 + b*64 + w] = __float2half_rn(s * (1.0f/64.0f));
        }
        for (int i = t; i < 4096; i += 256)
            g_xh[(size_t)bc * 4096 + i] = __float2half_rn(sm[(i >> 6) * 65 + (i & 63)]);
        return;
    }
    int i = (blockIdx.x - 4096) * 256 + threadIdx.x;
    if (i < 196608) {                       // Wqkv fp16
        int r = i >> 8, k = i & 255;
        float v;
        if (r < 128)      v = ps.p[2][r]     * ps.p[1][r*256+k];
        else if (r < 256) v = ps.p[5][r-128] * ps.p[4][(r-128)*256+k];
        else              v = ps.p[8][r-256] * ps.p[7][(r-256)*256+k];
        g_Wqkv_h[i] = __float2half_rn(v); return;
    }
    i -= 196608;
    if (i < 196608) {                       // Wvg1 fp16
        int r = i >> 8, k = i & 255;
        float v = (r < 512) ? ps.p[8][r] * ps.p[7][r*256+k]
                            : ps.p[24][r-512] * ps.p[23][(r-512)*256+k];
        g_Wvg1_h[i] = __float2half_rn(v);
        return;
    }
    i -= 196608;
    if (i < 262144) { int r = i >> 9; g_Wxx_h[0][i] = __float2half_rn(ps.p[15][r] * ps.p[14][i]); return; }
    i -= 262144;
    if (i < 262144) { int r = i >> 9; g_Wxx_h[1][i] = __float2half_rn(ps.p[18][r] * ps.p[17][i]); return; }
    i -= 262144;
    if (i < 196608) {                       // Wfin fp16
        int r = i / 768, c = i % 768;
        float v = (c < 512) ? ps.p[21][r] * ps.p[20][r*512+c]
                            : ps.p[30][r] * ps.p[29][r*256+(c-512)];
        g_Wfin_h[i] = __float2half_rn(v);
        return;
    }
    i -= 196608;
    if (i < 2304) { g_wdw[i] = ps.p[27][i/9] * ps.p[26][i]; return; }
    i -= 2304;
    if (i < 32768) {
        int t = i >> 13, rest = i & 8191;
        int c = rest >> 6, n = rest & 63;
        float coord = 0.25f * (float)n - 0.375f;
        coord = fminf(fmaxf(coord, 0.0f), 15.0f);
        int lo = (int)floorf(coord);
        int hi = min(lo + 1, 15);
        float tf = coord - (float)lo;
        const float* src = ps.p[10 + t];
        g_pos[t][c*64 + n] = src[c*16+lo] * (1.0f - tf) + src[c*16+hi] * tf;
    }
}

// ---------------- axial attention (256 threads) ----------------
__global__ void attn_kernel() {
    int bid = blockIdx.x;
    int br = bid >> 7, b = (bid >> 3) & 15, h = bid & 7;
    __shared__ float qs[16][64], ks[16][64], vs[64][64], ps[64][65];
    __shared__ float red1[4][64], red2[4][64];
    int t = threadIdx.x;
    int n = t & 63, g = t >> 6;
    for (int i = t; i < 1024; i += 256) {
        int kd = i >> 6, nn = i & 63;
        qs[kd][nn] = g_q[br][(h*16+kd)*1024 + b*64 + nn];
        ks[kd][nn] = g_k[br][(h*16+kd)*1024 + b*64 + nn];
    }
    for (int i = t; i < 4096; i += 256) {
        int d = i >> 6, nn = i & 63;
        vs[d][nn] = g_vax[br][(h*64+d)*1024 + b*64 + nn];
    }
    __syncthreads();
    float q[16];
    #pragma unroll
    for (int kd = 0; kd < 16; kd++) q[kd] = qs[kd][n];
    float mx = -1e30f;
    #pragma unroll
    for (int mm = 0; mm < 16; mm++) {
        int m = g * 16 + mm;
        float s = 0.f;
        #pragma unroll
        for (int kd = 0; kd < 16; kd++) s = fmaf(q[kd], ks[kd][m], s);
        s *= 0.25f;
        ps[n][m] = s;
        mx = fmaxf(mx, s);
    }
    red1[g][n] = mx;
    __syncthreads();
    float mxa = fmaxf(fmaxf(red1[0][n], red1[1][n]), fmaxf(red1[2][n], red1[3][n]));
    float sum = 0.f;
    #pragma unroll
    for (int mm = 0; mm < 16; mm++) {
        int m = g * 16 + mm;
        float e = __expf(ps[n][m] - mxa);
        ps[n][m] = e;
        sum += e;
    }
    red2[g][n] = sum;
    __syncthreads();
    float inv = 1.0f / (red2[0][n] + red2[1][n] + red2[2][n] + red2[3][n]);
    #pragma unroll
    for (int dd = 0; dd < 16; dd++) {
        int d = g * 16 + dd;
        float o = 0.f;
        #pragma unroll 8
        for (int m = 0; m < 64; m++) o = fmaf(ps[n][m], vs[d][m], o);
        g_axh[br][(h*64+d)*1024 + b*64 + n] = __float2half_rn(fmaxf(o * inv, 0.0f));
    }
}

// ---------------- depthwise 3x3: padded tile + rolling registers --------
// smem 66x68 fp32 zero-padded; thread (w = tid&63, hb = tid>>6) computes a
// 16-px column strip with 3 fresh smem loads per pixel (register rotation).
__global__ void dw_kernel(const float* __restrict__ b_dw) {
    int bc = blockIdx.x;
    int c = bc & 255;
    __shared__ float sm[66][68];
    const __half* gp = &g_g1h[(size_t)bc * 4096];
    int t = threadIdx.x;
    // zero borders + interior fill
    for (int i = t; i < 66 * 68; i += 256)
        ((float*)sm)[i] = 0.f;
    __syncthreads();
    for (int i = t; i < 4096; i += 256)
        sm[(i >> 6) + 1][(i & 63) + 1] = __half2float(gp[i]);
    __syncthreads();
    float w9[9];
    #pragma unroll
    for (int j = 0; j < 9; j++) w9[j] = g_wdw[c*9 + j];
    float bias = b_dw[c];

    const int w = t & 63, hb = t >> 6;
    const int h0 = hb * 16;                 // real row range [h0, h0+16)
    // padded indices: row r = h + 1, cols w, w+1, w+2
    float a0 = sm[h0][w],     a1 = sm[h0][w+1],     a2 = sm[h0][w+2];
    float b0 = sm[h0+1][w],   b1 = sm[h0+1][w+1],   b2 = sm[h0+1][w+2];
    __half* outp = &g_g2b[(size_t)bc * 4096 + h0 * 64 + w];
    #pragma unroll
    for (int i = 0; i < 16; i++) {
        float c0 = sm[h0+2+i][w], c1 = sm[h0+2+i][w+1], c2 = sm[h0+2+i][w+2];
        float s = bias;
        s = fmaf(a0, w9[0], s); s = fmaf(a1, w9[1], s); s = fmaf(a2, w9[2], s);
        s = fmaf(b0, w9[3], s); s = fmaf(b1, w9[4], s); s = fmaf(b2, w9[5], s);
        s = fmaf(c0, w9[6], s); s = fmaf(c1, w9[7], s); s = fmaf(c2, w9[8], s);
        outp[i * 64] = __float2half_rn(fmaxf(s, 0.0f));
        a0 = b0; a1 = b1; a2 = b2;
        b0 = c0; b1 = c1; b2 = c2;
    }
}

// ---------------- HMMA GEMM (modes 1, 5, 6, 7) ----------------
// CTA 256 thr. BMt=128 (mode 1): warps 4(m)x2(n), warp 32x64.
//              BMt=64 (modes 5,6,7): warps 2(m)x4(n), warp 32x32.
// fp16 x fp16, fp32 acc. 3-stage cp.async pipeline.
// MODE 1: W=Wvg1 (K=256), B=xh   -> p fp16 (relu(v+xx)) / g1 fp16
// MODE 5: W=Wqkv (K=256), B=xmh[z] -> q/k (+pos+bias) / vax (+bias) fp32
// MODE 6: W=Wxx[z] (K=512), B=axh[z] -> xx fp32 (+bias)
// MODE 7: W=Wfin (K=768): c<8 -> accP (B=pb), c>=8 -> accG (B=g2b);
//         out = (accP + b_proj) * hsig(accG + b_pw)
#define MM_SMEM128 (3 * 35840)
#define MM_SMEM64  (3 * 26624)

template <int MODE>
__global__ void __launch_bounds__(256) mm_gemm(
        const float* __restrict__ bias0,
        const float* __restrict__ bias1,
        const float* __restrict__ bias2,
        float* __restrict__ outp) {
    extern __shared__ char smem[];
    constexpr int K       = (MODE == 6) ? 512 : (MODE == 7) ? 768 : 256;
    constexpr int NC      = K / 64;
    constexpr int NCP     = (MODE == 7) ? 8 : NC;
    constexpr int KSTRIDE = K;
    constexpr bool AX     = (MODE == 5 || MODE == 6);
    constexpr int BMt     = (MODE == 1) ? 128 : 64;
    constexpr int WMC     = BMt / 32;
    constexpr int NP      = WMC;
    constexpr uint32_t BOFF = BMt * 144;
    constexpr uint32_t STG  = BMt * 144 + 17408;
    const int tid = threadIdx.x, lane = tid & 31, wid = tid >> 5;
    const int wm = wid % WMC, wn = wid / WMC;
    const int m0 = blockIdx.x * BMt;
    const int pt = blockIdx.y;
    const int bz = AX ? blockIdx.z : 0;
    const int b_ = AX ? 0 : (pt >> 5);
    const int hw0 = AX ? (pt << 7) : ((pt & 31) << 7);

    const uint32_t sb = smem_u32(smem);
    const __half* Wh = (MODE == 1) ? g_Wvg1_h
                     : (MODE == 5) ? g_Wqkv_h
                     : (MODE == 6) ? g_Wxx_h[bz] : g_Wfin_h;
    const __half* Bg = (MODE == 1) ? g_xh
                     : (MODE == 5) ? g_xmh[bz]
                     : (MODE == 6) ? g_axh[bz] : g_pb;

    float accP[2][2*NP][4], accG[2][2*NP][4];
    #pragma unroll
    for (int mf = 0; mf < 2; mf++)
        #pragma unroll
        for (int nf = 0; nf < 2*NP; nf++)
            #pragma unroll
            for (int j = 0; j < 4; j++) { accP[mf][nf][j] = 0.f; accG[mf][nf][j] = 0.f; }

    auto FILL = [&](int c) {
        const uint32_t st = sb + (uint32_t)(c % 3) * STG;
        const int kc = c * 64;
        #pragma unroll
        for (int i = 0; i < BMt/32; i++) {     // A: BMt x 64 fp16
            int idx = tid + i * 256;
            int m = idx >> 3, k8 = (idx & 7) << 3;
            size_t g = (size_t)(m0 + m) * KSTRIDE + kc + k8;
            CP16(st + (uint32_t)(m * 144 + k8 * 2), Wh + g);
        }
        #pragma unroll
        for (int i = 0; i < 4; i++) {          // B: 64k x 128px fp16
            int idx = tid + i * 256;
            int k = idx >> 4, px8 = (idx & 15) << 3;
            const __half* src;
            size_t g;
            if (MODE == 7) {
                int kch = kc + k;
                if (kch < 512) { src = g_pb;  g = (((size_t)(b_ * 512 + kch)) << 12) + hw0 + px8; }
                else           { src = g_g2b; g = (((size_t)(b_ * 256 + kch - 512)) << 12) + hw0 + px8; }
            } else if (AX) {
                src = Bg; g = (size_t)(kc + k) * 1024 + hw0 + px8;
            } else {
                src = Bg; g = (((size_t)(b_ * 256 + kc + k)) << 12) + hw0 + px8;
            }
            CP16(st + BOFF + (uint32_t)(k * 272 + px8 * 2), src + g);
        }
    };

#define MM_CHUNK(ACC) do { \
        if (c + 1 < NC) { CP_WAIT(1); } else { CP_WAIT(0); } \
        __syncthreads(); \
        if (c + 2 < NC) { FILL(c + 2); CP_COMMIT(); } \
        const uint32_t st = sb + (uint32_t)(c % 3) * STG; \
        _Pragma("unroll") \
        for (int kk = 0; kk < 64; kk += 16) { \
            uint32_t ah[2][4]; \
            uint32_t aoff = st + (uint32_t)(((wm * 32 + (lane & 15)) * 72 \
                              + kk + ((lane >> 4) << 3)) * 2); \
            LDSM4(ah[0], aoff); \
            LDSM4(ah[1], aoff + 2304u); \
            _Pragma("unroll") \
            for (int np = 0; np < NP; np++) { \
                uint32_t bh[4]; \
                uint32_t boff = st + BOFF + (uint32_t)( \
                    ((kk + (lane & 7) + (((lane >> 3) & 1) << 3)) * 136 \
                     + wn * (16*NP) + np * 16 + ((lane >> 4) << 3)) * 2); \
                LDSM4T(bh, boff); \
                _Pragma("unroll") \
                for (int mf = 0; mf < 2; mf++) { \
                    mma16816(ACC[mf][2*np],   ah[mf], bh[0], bh[1]); \
                    mma16816(ACC[mf][2*np+1], ah[mf], bh[2], bh[3]); \
                } \
            } \
        } \
    } while (0)

    FILL(0); CP_COMMIT();
    FILL(1); CP_COMMIT();
    for (int c = 0; c < NCP; c++) MM_CHUNK(accP);
    if (MODE == 7)
        for (int c = NCP; c < NC; c++) MM_CHUNK(accG);
#undef MM_CHUNK

    // ---- epilogue ----
    #pragma unroll
    for (int mf = 0; mf < 2; mf++) {
        int r0 = m0 + wm * 32 + mf * 16 + (lane >> 2);
        #pragma unroll
        for (int nf = 0; nf < 2*NP; nf++) {
            int pxg = hw0 + wn * (16*NP) + nf * 8 + ((lane & 3) << 1);
            #pragma unroll
            for (int half = 0; half < 2; half++) {
                int m = r0 + half * 8;
                float v0 = accP[mf][nf][half * 2 + 0];
                float v1 = accP[mf][nf][half * 2 + 1];
                if (MODE == 1) {
                    if (m < 512) {
                        float bb = bias0[m];
                        int hh = pxg >> 6, ww = pxg & 63;
                        float xr = g_xx[0][(b_*512 + m)*64 + hh];
                        float2 xc = *(const float2*)&g_xx[1][(b_*512 + m)*64 + ww];
                        float p0 = fmaxf(v0 + bb + xr + xc.x, 0.f);
                        float p1 = fmaxf(v1 + bb + xr + xc.y, 0.f);
                        size_t o = (((size_t)(b_*512 + m)) << 12) + pxg;
                        *(uint32_t*)&g_pb[o] = hpack(p0, p1);
                    } else {
                        float bb = bias1[m - 512];
                        size_t o = (((size_t)((b_ << 8) + m - 512)) << 12) + pxg;
                        *(uint32_t*)&g_g1h[o] = hpack(v0 + bb, v1 + bb);
                    }
                } else if (MODE == 7) {
                    float bp = bias0[m], bw = bias1[m];
                    float g0 = hsig(accG[mf][nf][half * 2 + 0] + bw);
                    float g1 = hsig(accG[mf][nf][half * 2 + 1] + bw);
                    size_t o = (((size_t)((b_ << 8) + m)) << 12) + pxg;
                    float2 o2 = {(v0 + bp) * g0, (v1 + bp) * g1};
                    *(float2*)&outp[o] = o2;
                } else if (MODE == 5) {
                    int nn = pxg & 63;
                    float2 o2;
                    if (m < 128) {
                        float2 pv = *(const float2*)&g_pos[bz ? 2 : 0][m*64 + nn];
                        float bb = bias0[m];
                        o2.x = v0 + bb + pv.x; o2.y = v1 + bb + pv.y;
                        *(float2*)&g_q[bz][m*1024 + pxg] = o2;
                    } else if (m < 256) {
                        int mm = m - 128;
                        float2 pv = *(const float2*)&g_pos[bz ? 3 : 1][mm*64 + nn];
                        float bb = bias1[mm];
                        o2.x = v0 + bb + pv.x; o2.y = v1 + bb + pv.y;
                        *(float2*)&g_k[bz][mm*1024 + pxg] = o2;
                    } else {
                        int mm = m - 256;
                        float bb = bias2[mm];
                        o2.x = v0 + bb; o2.y = v1 + bb;
                        *(float2*)&g_vax[bz][mm*1024 + pxg] = o2;
                    }
                } else {  // MODE 6
                    int bb_ = pxg >> 6, nn = pxg & 63;
                    float bb = (bz ? bias1 : bias0)[m];
                    float2 o2 = {v0 + bb, v1 + bb};
                    *(float2*)&g_xx[bz][(bb_*512 + m)*64 + nn] = o2;
                }
            }
        }
    }
}

// ---------------------------------------------------------------------------
extern "C" void kernel_launch(void* const* d_in, const int* in_sizes, int n_in,
                              void* d_out, int out_size) {
    (void)in_sizes; (void)n_in; (void)out_size;
    P32 ps;
    for (int i = 0; i < 32; i++) ps.p[i] = (const float*)d_in[i];
    const float* x      = ps.p[0];
    const float* bq     = ps.p[3];
    const float* bk     = ps.p[6];
    const float* bv     = ps.p[9];
    const float* b_row  = ps.p[16];
    const float* b_col  = ps.p[19];
    const float* b_proj = ps.p[22];
    const float* b_sc   = ps.p[25];
    const float* b_dw   = ps.p[28];
    const float* b_pw   = ps.p[31];
    float* out = (float*)d_out;

    cudaFuncSetAttribute(mm_gemm<1>, cudaFuncAttributeMaxDynamicSharedMemorySize, MM_SMEM128);
    cudaFuncSetAttribute(mm_gemm<5>, cudaFuncAttributeMaxDynamicSharedMemorySize, MM_SMEM64);
    cudaFuncSetAttribute(mm_gemm<6>, cudaFuncAttributeMaxDynamicSharedMemorySize, MM_SMEM64);
    cudaFuncSetAttribute(mm_gemm<7>, cudaFuncAttributeMaxDynamicSharedMemorySize, MM_SMEM64);

    prep_reduce_kernel<<<8585, 256>>>(ps, x);
    mm_gemm<5><<<dim3(12, 8, 2), 256, MM_SMEM64>>>(bq, bk, bv, nullptr);
    attn_kernel<<<256, 256>>>();
    mm_gemm<6><<<dim3(8, 8, 2), 256, MM_SMEM64>>>(b_row, b_col, nullptr, nullptr);
    mm_gemm<1><<<dim3(6, 512), 256, MM_SMEM128>>>(bv, b_sc, nullptr, nullptr);
    dw_kernel<<<4096, 256>>>(b_dw);
    mm_gemm<7><<<dim3(4, 512), 256, MM_SMEM64>>>(b_proj, b_pw, nullptr, out);
}